// round 14
// baseline (speedup 1.0000x reference)
#include <cuda_runtime.h>
#include <cuda_bf16.h>
#include <cuda_fp16.h>
#include <math.h>
#include <stdint.h>

// Problem dims (fixed by the dataset)
#define BB   2
#define SS   2048
#define DD   1024
#define HH   16
#define KVH  8
#define DK   64
#define FD   2752
#define NL   4
#define VV   32000
#define MM   (BB*SS)          // 4096 token rows
#define KVN  (KVH*DK)         // 512

// ---------------- scratch (device globals: no allocations allowed) ----------
__device__ float g_x [MM*DD];
__device__ float g_q [MM*DD];
__device__ float g_kv[MM*1024];
__device__ float g_f1[(size_t)MM*FD];
__device__ float g_f2[(size_t)MM*FD];
__device__ float g_bkv[NL*1024];

// split activations (fp16 hi/lo)
__device__ __half g_hH [MM*DD],  g_hL [MM*DD];
__device__ __half g_oH [MM*DD],  g_oL [MM*DD];
__device__ __half g_kvH[MM*1024], g_kvL[MM*1024];
__device__ __half g_f1H[(size_t)MM*FD], g_f1L[(size_t)MM*FD];

// split transposed weights ([N][K] layout, fp16 hi/lo)
__device__ __half g_wqH [(size_t)NL*DD*DD],   g_wqL [(size_t)NL*DD*DD];
__device__ __half g_wkvH[(size_t)NL*1024*DD], g_wkvL[(size_t)NL*1024*DD];
__device__ __half g_woH [(size_t)NL*DD*DD],   g_woL [(size_t)NL*DD*DD];
__device__ __half g_w1H [(size_t)NL*DD*FD],   g_w1L [(size_t)NL*DD*FD];
__device__ __half g_w2H [(size_t)NL*DD*FD],   g_w2L [(size_t)NL*DD*FD];
__device__ __half g_w3H [(size_t)NL*FD*DD],   g_w3L [(size_t)NL*FD*DD];
__device__ __half g_ebH [(size_t)VV*DD],      g_ebL [(size_t)VV*DD];

// ---------------- fp16 split helper ----------------
__device__ __forceinline__ void split2(float x0, float x1,
                                       unsigned &hi, unsigned &lo) {
    __half2 h = __floats2half2_rn(x0, x1);
    float2 hf = __half22float2(h);
    __half2 l = __floats2half2_rn(x0 - hf.x, x1 - hf.y);
    hi = *reinterpret_cast<unsigned*>(&h);
    lo = *reinterpret_cast<unsigned*>(&l);
}

__device__ __forceinline__ unsigned smem_u32(const void* p) {
    unsigned r;
    asm("{ .reg .u64 t; cvta.to.shared.u64 t, %1; cvt.u32.u64 %0, t; }" : "=r"(r) : "l"(p));
    return r;
}

// ---------------- embedding gather ----------------
__global__ void embed_kernel(const int* __restrict__ tokens,
                             const float* __restrict__ emb,
                             float* __restrict__ x) {
    int row = blockIdx.x;
    int tok = tokens[row];
    const float4* src = (const float4*)(emb + (size_t)tok * DD);
    float4*       dst = (float4*)(x + (size_t)row * DD);
    dst[threadIdx.x] = src[threadIdx.x];
}

// ---------------- elementwise split (embed table) ----------------
__global__ void esplit_kernel(const float* __restrict__ W,
                              __half* __restrict__ H,
                              __half* __restrict__ L) {
    size_t i = ((size_t)blockIdx.x * 256 + threadIdx.x) * 4;
    float4 v = *(const float4*)(W + i);
    unsigned h0, l0, h1, l1;
    split2(v.x, v.y, h0, l0);
    split2(v.z, v.w, h1, l1);
    *(uint2*)(H + i) = make_uint2(h0, h1);
    *(uint2*)(L + i) = make_uint2(l0, l1);
}

// ---------------- transpose + split: W[K][N] -> H/L[N][K] ----------------
__global__ void tsplit_kernel(const float* __restrict__ W,
                              __half* __restrict__ H,
                              __half* __restrict__ L, int K, int N) {
    __shared__ float tile[32][33];
    int n0 = blockIdx.x * 32, k0 = blockIdx.y * 32;
    int tx = threadIdx.x, ty = threadIdx.y;
    #pragma unroll
    for (int i = 0; i < 32; i += 8)
        tile[ty + i][tx] = W[(size_t)(k0 + ty + i) * N + n0 + tx];
    __syncthreads();
    #pragma unroll
    for (int i = 0; i < 32; i += 8) {
        int n = n0 + ty + i, k = k0 + tx;
        float v = tile[tx][ty + i];
        __half h = __float2half_rn(v);
        H[(size_t)n * K + k] = h;
        L[(size_t)n * K + k] = __float2half_rn(v - __half2float(h));
    }
}

// ---------------- bias concat for merged KV GEMM ----------------
__global__ void bkv_kernel(const float* __restrict__ bk, const float* __restrict__ bv,
                           float* __restrict__ bkv) {
    int l = blockIdx.x, t = threadIdx.x;
    bkv[l * 1024 + t]       = bk[l * 512 + t];
    bkv[l * 1024 + 512 + t] = bv[l * 512 + t];
}

// ---------------- rmsnorm -> split output ----------------
__global__ void rmsnorm_split_kernel(const float* __restrict__ x,
                                     const float* __restrict__ g,
                                     __half* __restrict__ H,
                                     __half* __restrict__ L) {
    int row = blockIdx.x;
    const float4* xr = (const float4*)(x + (size_t)row * DD);
    float4 v = xr[threadIdx.x];
    float ss = v.x*v.x + v.y*v.y + v.z*v.z + v.w*v.w;
    #pragma unroll
    for (int o = 16; o; o >>= 1) ss += __shfl_xor_sync(0xffffffffu, ss, o);
    __shared__ float red[8];
    if ((threadIdx.x & 31) == 0) red[threadIdx.x >> 5] = ss;
    __syncthreads();
    if (threadIdx.x < 8) {
        float r = red[threadIdx.x];
        #pragma unroll
        for (int o = 4; o; o >>= 1) r += __shfl_xor_sync(0xffu, r, o);
        if (threadIdx.x == 0) red[0] = r;
    }
    __syncthreads();
    float inv = rsqrtf(red[0] * (1.0f / DD) + 1e-6f);
    const float4* g4 = (const float4*)g;
    float4 gg = g4[threadIdx.x];
    float o0 = v.x*inv*gg.x, o1 = v.y*inv*gg.y, o2 = v.z*inv*gg.z, o3 = v.w*inv*gg.w;
    unsigned h0, l0, h1, l1;
    split2(o0, o1, h0, l0);
    split2(o2, o3, h1, l1);
    size_t base = (size_t)row * DD + threadIdx.x * 4;
    *(uint2*)(H + base) = make_uint2(h0, h1);
    *(uint2*)(L + base) = make_uint2(l0, l1);
}

// ---------------- kv: rope(k part) + split into fp16 hi/lo ----------------
__global__ void kvsplit_rope_kernel(const float* __restrict__ kv,
                                    const float* __restrict__ cosb,
                                    const float* __restrict__ sinb,
                                    __half* __restrict__ H,
                                    __half* __restrict__ L) {
    int row = blockIdx.x;
    int s   = row & (SS - 1);
    for (int pp = threadIdx.x; pp < 512; pp += 256) {
        int col = pp * 2;
        float2 v = *(const float2*)(kv + (size_t)row * 1024 + col);
        if (col < 512) {
            int p = (col & 63) >> 1;
            float c = cosb[s * 32 + p], sn = sinb[s * 32 + p];
            float xr = v.x, xi = v.y;
            v.x = xr * c - xi * sn;
            v.y = xr * sn + xi * c;
        }
        unsigned h_, l_;
        split2(v.x, v.y, h_, l_);
        ((unsigned*)H)[(size_t)row * 512 + pp] = h_;
        ((unsigned*)L)[(size_t)row * 512 + pp] = l_;
    }
}

// ---- fp16-input MMA with fp32 accumulator ----
#define F16MMA(D, Ar, Br)                                                     \
    asm volatile(                                                             \
        "mma.sync.aligned.m16n8k16.row.col.f32.f16.f16.f32 "                  \
        "{%0,%1,%2,%3}, {%4,%5,%6,%7}, {%8,%9}, {%0,%1,%2,%3};"               \
        : "+f"(D[0]), "+f"(D[1]), "+f"(D[2]), "+f"(D[3])                      \
        : "r"(Ar[0]), "r"(Ar[1]), "r"(Ar[2]), "r"(Ar[3]),                     \
          "r"(Br[0]), "r"(Br[1]))

// ---- fp16-input MMA with fp16 accumulator (hypothesized 2x rate) ----
#define F16MMA2(D0, D1, Ar, Br)                                               \
    asm volatile(                                                             \
        "mma.sync.aligned.m16n8k16.row.col.f16.f16.f16.f16 "                  \
        "{%0,%1}, {%2,%3,%4,%5}, {%6,%7}, {%0,%1};"                           \
        : "+r"(D0), "+r"(D1)                                                  \
        : "r"(Ar[0]), "r"(Ar[1]), "r"(Ar[2]), "r"(Ar[3]),                     \
          "r"(Br[0]), "r"(Br[1]))

#define LDSM4(R0, R1, R2, R3, ADDR)                                           \
    asm volatile("ldmatrix.sync.aligned.m8n8.x4.shared.b16 {%0,%1,%2,%3}, [%4];" \
        : "=r"(R0), "=r"(R1), "=r"(R2), "=r"(R3) : "r"(ADDR))

#define LDSM4T(R0, R1, R2, R3, ADDR)                                          \
    asm volatile("ldmatrix.sync.aligned.m8n8.x4.trans.shared.b16 {%0,%1,%2,%3}, [%4];" \
        : "=r"(R0), "=r"(R1), "=r"(R2), "=r"(R3) : "r"(ADDR))

// ======== flash attention v2: cp.async fp16 tiles + ldmatrix, 3x split =====
// rope(Q) fused into the Q-fragment load.
#define ARS 144
#define ATILE (64 * ARS)
#define ASTAGE (4 * ATILE)
#define ASMEM (2 * ASTAGE)        // 73728

__global__ __launch_bounds__(128)
void attn_tc_kernel(const float* __restrict__ Q,
                    const __half* __restrict__ kvH,
                    const __half* __restrict__ kvL,
                    const float* __restrict__ cosb, const float* __restrict__ sinb,
                    __half* __restrict__ OH, __half* __restrict__ OL) {
    extern __shared__ char asmem[];
    const unsigned sb0 = smem_u32(asmem);
    const int qb   = gridDim.x - 1 - blockIdx.x;
    const int hd   = blockIdx.y;
    const int b    = blockIdx.z;
    const int kh   = hd >> 1;
    const int t    = threadIdx.x;
    const int lane = t & 31;
    const int w    = t >> 5;
    const int lq   = lane >> 2;
    const int lr   = lane & 3;

    unsigned qaH[4][4], qaL[4][4];
    {
        const int r0 = qb * 64 + w * 16 + lq;
        const int r1 = r0 + 8;
        const float* q0p = Q + ((size_t)(b * SS + r0) * HH + hd) * DK;
        const float* q1p = q0p + (size_t)8 * HH * DK;
        #pragma unroll
        for (int kb = 0; kb < 4; kb++) {
            int p0 = kb * 8 + lr, p1 = kb * 8 + 4 + lr;
            float c00 = cosb[r0 * 32 + p0], s00 = sinb[r0 * 32 + p0];
            float c10 = cosb[r1 * 32 + p0], s10 = sinb[r1 * 32 + p0];
            float c01 = cosb[r0 * 32 + p1], s01 = sinb[r0 * 32 + p1];
            float c11 = cosb[r1 * 32 + p1], s11 = sinb[r1 * 32 + p1];
            float2 v0 = *(const float2*)(q0p + kb * 16 + 2 * lr);
            float2 v1 = *(const float2*)(q1p + kb * 16 + 2 * lr);
            float2 v2 = *(const float2*)(q0p + kb * 16 + 8 + 2 * lr);
            float2 v3 = *(const float2*)(q1p + kb * 16 + 8 + 2 * lr);
            float a0 = v0.x * c00 - v0.y * s00, b0 = v0.x * s00 + v0.y * c00;
            float a1 = v1.x * c10 - v1.y * s10, b1 = v1.x * s10 + v1.y * c10;
            float a2 = v2.x * c01 - v2.y * s01, b2 = v2.x * s01 + v2.y * c01;
            float a3 = v3.x * c11 - v3.y * s11, b3 = v3.x * s11 + v3.y * c11;
            split2(a0 * 0.125f, b0 * 0.125f, qaH[kb][0], qaL[kb][0]);
            split2(a1 * 0.125f, b1 * 0.125f, qaH[kb][1], qaL[kb][1]);
            split2(a2 * 0.125f, b2 * 0.125f, qaH[kb][2], qaL[kb][2]);
            split2(a3 * 0.125f, b3 * 0.125f, qaH[kb][3], qaL[kb][3]);
        }
    }

    float acc[8][4] = {};
    float m0 = -1e30f, m1 = -1e30f, l0 = 0.f, l1 = 0.f;
    const int ntiles = qb + 1;

    const unsigned aOff = (unsigned)(lane & 15) * ARS + (unsigned)(lane >> 4) * 16;
    const unsigned bOff = (unsigned)((lane >> 4) * 8 + (lane & 7)) * ARS
                        + (unsigned)((lane >> 3) & 1) * 16;

    auto issue_tile = [&](int kt) {
        const int kbase = kt * 64;
        unsigned sb = sb0 + (kt & 1) * ASTAGE;
        #pragma unroll
        for (int i = 0; i < 16; i++) {
            int c   = t + i * 128;
            int buf = c >> 9;
            int cc  = c & 511;
            int row = cc >> 3, q8 = cc & 7;
            const __half* bp = (buf & 1) ? kvL : kvH;
            int voff = (buf >> 1) * 512;
            const __half* src = bp + (size_t)(b * SS + kbase + row) * 1024
                                   + voff + kh * 64 + q8 * 8;
            unsigned dst = sb + buf * ATILE + row * ARS + q8 * 16;
            asm volatile("cp.async.cg.shared.global [%0], [%1], 16;"
                         :: "r"(dst), "l"(src) : "memory");
        }
        asm volatile("cp.async.commit_group;" ::: "memory");
    };

    issue_tile(0);
    for (int kt = 0; kt < ntiles; kt++) {
        if (kt + 1 < ntiles) {
            issue_tile(kt + 1);
            asm volatile("cp.async.wait_group 1;" ::: "memory");
        } else {
            asm volatile("cp.async.wait_group 0;" ::: "memory");
        }
        __syncthreads();

        const unsigned stb = sb0 + (kt & 1) * ASTAGE;
        const int kbase = kt * 64;

        float s[8][4] = {};
        #pragma unroll
        for (int kb = 0; kb < 4; kb++) {
            unsigned kfH[4][4], kfL[4][4];
            #pragma unroll
            for (int ng = 0; ng < 4; ng++) {
                unsigned ad = stb + (unsigned)(ng * 16) * ARS + kb * 32 + bOff;
                LDSM4(kfH[ng][0], kfH[ng][1], kfH[ng][2], kfH[ng][3], ad);
                LDSM4(kfL[ng][0], kfL[ng][1], kfL[ng][2], kfL[ng][3], ad + ATILE);
            }
            #pragma unroll
            for (int ng = 0; ng < 4; ng++) {
                F16MMA(s[ng*2],   qaH[kb], (kfH[ng] + 0));
                F16MMA(s[ng*2],   qaL[kb], (kfH[ng] + 0));
                F16MMA(s[ng*2],   qaH[kb], (kfL[ng] + 0));
                F16MMA(s[ng*2+1], qaH[kb], (kfH[ng] + 2));
                F16MMA(s[ng*2+1], qaL[kb], (kfH[ng] + 2));
                F16MMA(s[ng*2+1], qaH[kb], (kfL[ng] + 2));
            }
        }

        if (kt == qb) {
            int row0 = qb * 64 + w * 16 + lq;
            #pragma unroll
            for (int ni = 0; ni < 8; ni++) {
                int col = kbase + ni * 8 + 2 * lr;
                if (col     > row0)     s[ni][0] = -1e30f;
                if (col + 1 > row0)     s[ni][1] = -1e30f;
                if (col     > row0 + 8) s[ni][2] = -1e30f;
                if (col + 1 > row0 + 8) s[ni][3] = -1e30f;
            }
        }

        float mt0 = -1e30f, mt1 = -1e30f;
        #pragma unroll
        for (int ni = 0; ni < 8; ni++) {
            mt0 = fmaxf(mt0, fmaxf(s[ni][0], s[ni][1]));
            mt1 = fmaxf(mt1, fmaxf(s[ni][2], s[ni][3]));
        }
        mt0 = fmaxf(mt0, __shfl_xor_sync(0xffffffffu, mt0, 1));
        mt0 = fmaxf(mt0, __shfl_xor_sync(0xffffffffu, mt0, 2));
        mt1 = fmaxf(mt1, __shfl_xor_sync(0xffffffffu, mt1, 1));
        mt1 = fmaxf(mt1, __shfl_xor_sync(0xffffffffu, mt1, 2));
        float mn0 = fmaxf(m0, mt0), mn1 = fmaxf(m1, mt1);
        float c0 = __expf(m0 - mn0), c1 = __expf(m1 - mn1);
        m0 = mn0; m1 = mn1;
        float rs0 = 0.f, rs1 = 0.f;
        #pragma unroll
        for (int ni = 0; ni < 8; ni++) {
            s[ni][0] = __expf(s[ni][0] - mn0);
            s[ni][1] = __expf(s[ni][1] - mn0);
            s[ni][2] = __expf(s[ni][2] - mn1);
            s[ni][3] = __expf(s[ni][3] - mn1);
            rs0 += s[ni][0] + s[ni][1];
            rs1 += s[ni][2] + s[ni][3];
        }
        rs0 += __shfl_xor_sync(0xffffffffu, rs0, 1);
        rs0 += __shfl_xor_sync(0xffffffffu, rs0, 2);
        rs1 += __shfl_xor_sync(0xffffffffu, rs1, 1);
        rs1 += __shfl_xor_sync(0xffffffffu, rs1, 2);
        l0 = l0 * c0 + rs0;
        l1 = l1 * c1 + rs1;
        #pragma unroll
        for (int dn = 0; dn < 8; dn++) {
            acc[dn][0] *= c0; acc[dn][1] *= c0;
            acc[dn][2] *= c1; acc[dn][3] *= c1;
        }

        #pragma unroll
        for (int kb = 0; kb < 4; kb++) {
            unsigned aPH[4], aPL[4];
            split2(s[2*kb][0],   s[2*kb][1],   aPH[0], aPL[0]);
            split2(s[2*kb][2],   s[2*kb][3],   aPH[1], aPL[1]);
            split2(s[2*kb+1][0], s[2*kb+1][1], aPH[2], aPL[2]);
            split2(s[2*kb+1][2], s[2*kb+1][3], aPH[3], aPL[3]);
            #pragma unroll
            for (int dn = 0; dn < 4; dn++) {
                unsigned vfH[4], vfL[4];
                unsigned ad = stb + 2 * ATILE + (unsigned)(kb * 16) * ARS
                            + (unsigned)(dn * 16) * 2 + aOff;
                LDSM4T(vfH[0], vfH[1], vfH[2], vfH[3], ad);
                LDSM4T(vfL[0], vfL[1], vfL[2], vfL[3], ad + ATILE);
                float* acc0 = acc[dn * 2];
                float* acc1 = acc[dn * 2 + 1];
                F16MMA(acc0, aPH, (vfH + 0));
                F16MMA(acc0, aPL, (vfH + 0));
                F16MMA(acc0, aPH, (vfL + 0));
                F16MMA(acc1, aPH, (vfH + 2));
                F16MMA(acc1, aPL, (vfH + 2));
                F16MMA(acc1, aPH, (vfL + 2));
            }
        }
        __syncthreads();
    }

    float inv0 = 1.f / l0, inv1 = 1.f / l1;
    int row0 = qb * 64 + w * 16 + lq;
    size_t b0 = ((size_t)(b * SS + row0) * HH + hd) * DK;
    size_t b1 = b0 + (size_t)8 * HH * DK;
    #pragma unroll
    for (int dn = 0; dn < 8; dn++) {
        int d = dn * 8 + 2 * lr;
        unsigned h_, l_;
        split2(acc[dn][0] * inv0, acc[dn][1] * inv0, h_, l_);
        *(unsigned*)(OH + b0 + d) = h_;
        *(unsigned*)(OL + b0 + d) = l_;
        split2(acc[dn][2] * inv1, acc[dn][3] * inv1, h_, l_);
        *(unsigned*)(OH + b1 + d) = h_;
        *(unsigned*)(OL + b1 + d) = l_;
    }
}

// ========== fp16 split GEMM: main MMA f32-acc, corrections f16-acc =========
// C[M,N] = (AH+AL)[M][K] @ (BH+BL)[N][K]^T (+bias)(+residual), fp32 out.
// Block tile 128xBN (BN=128 or 256), 256 threads, 8 warps (2x4),
// warp tile 64x(BN/4).
#define G_BK 32
#define G_RS 80

template<int BN>
__global__ __launch_bounds__(256)
void gemm_bb_kernel(const __half* __restrict__ AH_, const __half* __restrict__ AL_,
                    const __half* __restrict__ BH_, const __half* __restrict__ BL_,
                    const float* __restrict__ bias, const float* __restrict__ res,
                    float* __restrict__ C, int Nd, int Kd) {
    constexpr int NG      = BN / 64;
    constexpr unsigned OFF_AL = 128 * G_RS;
    constexpr unsigned OFF_BH = 256 * G_RS;
    constexpr unsigned OFF_BL = (256 + BN) * G_RS;
    constexpr unsigned STAGE  = (256 + 2 * BN) * G_RS;
    constexpr int CH_B    = BN * 4;

    extern __shared__ char smem[];
    const unsigned sbase = smem_u32(smem);
    const int t    = threadIdx.x;
    const int lane = t & 31;
    const int warp = t >> 5;
    const int wm   = warp >> 2;
    const int wn   = warp & 3;
    const int bm   = blockIdx.y * 128;
    const int bn   = blockIdx.x * BN;

    float acc[4][2 * NG][4] = {};
    const int nkt = Kd / G_BK;

    auto issue_stage = [&](int kt) {
        const int k0 = kt * G_BK;
        unsigned sb = sbase + (kt % 3) * STAGE;
        #pragma unroll
        for (int i = 0; i < 4; i++) {
            int c = t + i * 256;
            const __half* base = (c < 512) ? AH_ : AL_;
            unsigned offt = (c < 512) ? 0u : OFF_AL;
            int cc = c & 511;
            int row = cc >> 2, quad = cc & 3;
            const __half* src = base + (size_t)(bm + row) * Kd + k0 + quad * 8;
            unsigned dst = sb + offt + row * G_RS + quad * 16;
            asm volatile("cp.async.cg.shared.global [%0], [%1], 16;"
                         :: "r"(dst), "l"(src) : "memory");
        }
        #pragma unroll
        for (int i = 0; i < BN / 32; i++) {
            int c = t + i * 256;
            const __half* base = (c < CH_B) ? BH_ : BL_;
            unsigned offt = (c < CH_B) ? OFF_BH : OFF_BL;
            int cc = c & (CH_B - 1);
            int row = cc >> 2, quad = cc & 3;
            const __half* src = base + (size_t)(bn + row) * Kd + k0 + quad * 8;
            unsigned dst = sb + offt + row * G_RS + quad * 16;
            int vsz = (bn + row < Nd) ? 16 : 0;
            asm volatile("cp.async.cg.shared.global [%0], [%1], 16, %2;"
                         :: "r"(dst), "l"(src), "r"(vsz) : "memory");
        }
        asm volatile("cp.async.commit_group;" ::: "memory");
    };

    issue_stage(0);
    issue_stage(1);

    const int m0 = wm * 64;
    const int n0 = wn * (BN / 4);
    const int lq = lane >> 2;
    const int lr = lane & 3;
    const unsigned aRowOff = (unsigned)(lane & 15) * G_RS + (unsigned)(lane >> 4) * 16;
    const unsigned bRowOff = ((unsigned)((lane >> 4) * 8 + (lane & 7))) * G_RS
                           + (unsigned)((lane >> 3) & 1) * 16;

    for (int kt = 0; kt < nkt; kt++) {
        asm volatile("cp.async.wait_group 1;" ::: "memory");
        __syncthreads();
        if (kt + 2 < nkt) issue_stage(kt + 2);
        else asm volatile("cp.async.commit_group;" ::: "memory");

        const unsigned stb = sbase + (kt % 3) * STAGE;
        #pragma unroll
        for (int ks = 0; ks < 2; ks++) {
            unsigned aH[4][4], aL[4][4], bH[NG][4], bL[NG][4];
            const unsigned ksb = ks * 32;
            #pragma unroll
            for (int mi = 0; mi < 4; mi++) {
                unsigned ah = stb + (m0 + mi * 16) * G_RS + ksb + aRowOff;
                unsigned al = ah + OFF_AL;
                LDSM4(aH[mi][0], aH[mi][1], aH[mi][2], aH[mi][3], ah);
                LDSM4(aL[mi][0], aL[mi][1], aL[mi][2], aL[mi][3], al);
            }
            #pragma unroll
            for (int ng = 0; ng < NG; ng++) {
                unsigned bhh = stb + OFF_BH + (n0 + ng * 16) * G_RS + ksb + bRowOff;
                unsigned bll = bhh + (unsigned)(BN * G_RS);
                LDSM4(bH[ng][0], bH[ng][1], bH[ng][2], bH[ng][3], bhh);
                LDSM4(bL[ng][0], bL[ng][1], bL[ng][2], bL[ng][3], bll);
            }
            #pragma unroll
            for (int mi = 0; mi < 4; mi++)
                #pragma unroll
                for (int ng = 0; ng < NG; ng++) {
                    float* acc0 = acc[mi][ng * 2];
                    float* acc1 = acc[mi][ng * 2 + 1];
                    // main products (fp32 acc)
                    F16MMA(acc0, aH[mi], (bH[ng] + 0));
                    F16MMA(acc1, aH[mi], (bH[ng] + 2));
                    // correction products (fp16 acc, drained immediately)
                    unsigned cd0 = 0, cd1 = 0, ce0 = 0, ce1 = 0;
                    F16MMA2(cd0, cd1, aL[mi], (bH[ng] + 0));
                    F16MMA2(cd0, cd1, aH[mi], (bL[ng] + 0));
                    F16MMA2(ce0, ce1, aL[mi], (bH[ng] + 2));
                    F16MMA2(ce0, ce1, aH[mi], (bL[ng] + 2));
                    float2 f;
                    f = __half22float2(*(__half2*)&cd0); acc0[0] += f.x; acc0[1] += f.y;
                    f = __half22float2(*(__half2*)&cd1); acc0[2] += f.x; acc0[3] += f.y;
                    f = __half22float2(*(__half2*)&ce0); acc1[0] += f.x; acc1[1] += f.y;
                    f = __half22float2(*(__half2*)&ce1); acc1[2] += f.x; acc1[3] += f.y;
                }
        }
    }

    #pragma unroll
    for (int mi = 0; mi < 4; mi++) {
        int row = bm + m0 + mi * 16 + lq;
        #pragma unroll
        for (int ni = 0; ni < 2 * NG; ni++) {
            int col = bn + n0 + ni * 8 + lr * 2;
            if (col < Nd) {
                float v0 = acc[mi][ni][0], v1 = acc[mi][ni][1];
                float v2 = acc[mi][ni][2], v3 = acc[mi][ni][3];
                if (bias) {
                    float bx = bias[col], by = bias[col + 1];
                    v0 += bx; v1 += by; v2 += bx; v3 += by;
                }
                size_t o0 = (size_t)row * Nd + col;
                size_t o1 = (size_t)(row + 8) * Nd + col;
                if (res) {
                    v0 += res[o0]; v1 += res[o0 + 1];
                    v2 += res[o1]; v3 += res[o1 + 1];
                }
                C[o0] = v0; C[o0 + 1] = v1;
                C[o1] = v2; C[o1 + 1] = v3;
            }
        }
    }
}

#define SM128 ((256 + 2 * 128) * G_RS * 3)    // 122880
#define SM256 ((256 + 2 * 256) * G_RS * 3)    // 184320

// ---------------- silu(f1)*f2 -> split ----------------
__global__ void silumul_split_kernel(const float* __restrict__ f1,
                                     const float* __restrict__ f2,
                                     __half* __restrict__ H,
                                     __half* __restrict__ L) {
    size_t i = (size_t)blockIdx.x * 256 + threadIdx.x;
    float2 a = ((const float2*)f1)[i];
    float2 b = ((const float2*)f2)[i];
    float g0 = a.x / (1.0f + __expf(-a.x)) * b.x;
    float g1 = a.y / (1.0f + __expf(-a.y)) * b.y;
    unsigned h_, l_;
    split2(g0, g1, h_, l_);
    ((unsigned*)H)[i] = h_;
    ((unsigned*)L)[i] = l_;
}

// ---------------- host driver ----------------
extern "C" void kernel_launch(void* const* d_in, const int* in_sizes, int n_in,
                              void* d_out, int out_size) {
    const int*   tokens = (const int*)  d_in[0];
    const float* emb    = (const float*)d_in[1];
    const float* wq = (const float*)d_in[2];
    const float* bq = (const float*)d_in[3];
    const float* wk = (const float*)d_in[4];
    const float* bk = (const float*)d_in[5];
    const float* wv = (const float*)d_in[6];
    const float* bv = (const float*)d_in[7];
    const float* wo = (const float*)d_in[8];
    const float* bo = (const float*)d_in[9];
    const float* w1 = (const float*)d_in[10];
    const float* b1 = (const float*)d_in[11];
    const float* w2 = (const float*)d_in[12];
    const float* b2 = (const float*)d_in[13];
    const float* w3 = (const float*)d_in[14];
    const float* b3 = (const float*)d_in[15];
    const float* g1 = (const float*)d_in[16];
    const float* g2 = (const float*)d_in[17];
    const float* gpost = (const float*)d_in[18];
    const float* fcos  = (const float*)d_in[19];
    const float* fsin  = (const float*)d_in[20];
    float* out = (float*)d_out;

    float *x, *q, *kv, *f1, *f2, *bkv;
    __half *hH, *hL, *oH, *oL, *kvH, *kvL, *f1H, *f1L;
    __half *wqH, *wqL, *wkvH, *wkvL, *woH, *woL;
    __half *w1H, *w1L, *w2H, *w2L, *w3H, *w3L, *ebH, *ebL;
    cudaGetSymbolAddress((void**)&x,   g_x);
    cudaGetSymbolAddress((void**)&q,   g_q);
    cudaGetSymbolAddress((void**)&kv,  g_kv);
    cudaGetSymbolAddress((void**)&f1,  g_f1);
    cudaGetSymbolAddress((void**)&f2,  g_f2);
    cudaGetSymbolAddress((void**)&bkv, g_bkv);
    cudaGetSymbolAddress((void**)&hH,  g_hH);   cudaGetSymbolAddress((void**)&hL,  g_hL);
    cudaGetSymbolAddress((void**)&oH,  g_oH);   cudaGetSymbolAddress((void**)&oL,  g_oL);
    cudaGetSymbolAddress((void**)&kvH, g_kvH);  cudaGetSymbolAddress((void**)&kvL, g_kvL);
    cudaGetSymbolAddress((void**)&f1H, g_f1H);  cudaGetSymbolAddress((void**)&f1L, g_f1L);
    cudaGetSymbolAddress((void**)&wqH, g_wqH);  cudaGetSymbolAddress((void**)&wqL, g_wqL);
    cudaGetSymbolAddress((void**)&wkvH, g_wkvH); cudaGetSymbolAddress((void**)&wkvL, g_wkvL);
    cudaGetSymbolAddress((void**)&woH, g_woH);  cudaGetSymbolAddress((void**)&woL, g_woL);
    cudaGetSymbolAddress((void**)&w1H, g_w1H);  cudaGetSymbolAddress((void**)&w1L, g_w1L);
    cudaGetSymbolAddress((void**)&w2H, g_w2H);  cudaGetSymbolAddress((void**)&w2L, g_w2L);
    cudaGetSymbolAddress((void**)&w3H, g_w3H);  cudaGetSymbolAddress((void**)&w3L, g_w3L);
    cudaGetSymbolAddress((void**)&ebH, g_ebH);  cudaGetSymbolAddress((void**)&ebL, g_ebL);

    cudaFuncSetAttribute(gemm_bb_kernel<128>,
                         cudaFuncAttributeMaxDynamicSharedMemorySize, SM128);
    cudaFuncSetAttribute(gemm_bb_kernel<256>,
                         cudaFuncAttributeMaxDynamicSharedMemorySize, SM256);
    cudaFuncSetAttribute(attn_tc_kernel,
                         cudaFuncAttributeMaxDynamicSharedMemorySize, ASMEM);

    // ---- conversions (inside graph) ----
    esplit_kernel<<<(VV * DD) / (256 * 4), 256>>>(emb, ebH, ebL);
    bkv_kernel<<<NL, 512>>>(bk, bv, bkv);
    dim3 tb(32, 8);
    for (int l = 0; l < NL; l++) {
        tsplit_kernel<<<dim3(DD / 32, DD / 32), tb>>>(
            wq + (size_t)l * DD * DD, wqH + (size_t)l * DD * DD, wqL + (size_t)l * DD * DD, DD, DD);
        tsplit_kernel<<<dim3(KVN / 32, DD / 32), tb>>>(
            wk + (size_t)l * DD * KVN,
            wkvH + (size_t)l * 1024 * DD, wkvL + (size_t)l * 1024 * DD, DD, KVN);
        tsplit_kernel<<<dim3(KVN / 32, DD / 32), tb>>>(
            wv + (size_t)l * DD * KVN,
            wkvH + (size_t)l * 1024 * DD + (size_t)512 * DD,
            wkvL + (size_t)l * 1024 * DD + (size_t)512 * DD, DD, KVN);
        tsplit_kernel<<<dim3(DD / 32, DD / 32), tb>>>(
            wo + (size_t)l * DD * DD, woH + (size_t)l * DD * DD, woL + (size_t)l * DD * DD, DD, DD);
        tsplit_kernel<<<dim3(FD / 32, DD / 32), tb>>>(
            w1 + (size_t)l * DD * FD, w1H + (size_t)l * DD * FD, w1L + (size_t)l * DD * FD, DD, FD);
        tsplit_kernel<<<dim3(FD / 32, DD / 32), tb>>>(
            w2 + (size_t)l * DD * FD, w2H + (size_t)l * DD * FD, w2L + (size_t)l * DD * FD, DD, FD);
        tsplit_kernel<<<dim3(DD / 32, FD / 32), tb>>>(
            w3 + (size_t)l * FD * DD, w3H + (size_t)l * FD * DD, w3L + (size_t)l * FD * DD, FD, DD);
    }

    embed_kernel<<<MM, 256>>>(tokens, emb, x);

    const int GY = MM / 128;    // 32
    for (int l = 0; l < NL; l++) {
        rmsnorm_split_kernel<<<MM, 256>>>(x, g1 + (size_t)l * DD, hH, hL);

        gemm_bb_kernel<256><<<dim3(DD / 256, GY), 256, SM256>>>(
            hH, hL, wqH + (size_t)l * DD * DD, wqL + (size_t)l * DD * DD,
            bq + (size_t)l * DD, nullptr, q, DD, DD);
        gemm_bb_kernel<256><<<dim3(1024 / 256, GY), 256, SM256>>>(
            hH, hL, wkvH + (size_t)l * 1024 * DD, wkvL + (size_t)l * 1024 * DD,
            bkv + (size_t)l * 1024, nullptr, kv, 1024, DD);

        kvsplit_rope_kernel<<<MM, 256>>>(kv, fcos, fsin, kvH, kvL);

        attn_tc_kernel<<<dim3(SS / 64, HH, BB), 128, ASMEM>>>(
            q, kvH, kvL, fcos, fsin, oH, oL);

        gemm_bb_kernel<256><<<dim3(DD / 256, GY), 256, SM256>>>(
            oH, oL, woH + (size_t)l * DD * DD, woL + (size_t)l * DD * DD,
            bo + (size_t)l * DD, x, x, DD, DD);

        rmsnorm_split_kernel<<<MM, 256>>>(x, g2 + (size_t)l * DD, hH, hL);

        int gnx = (FD + 255) / 256;   // 11
        gemm_bb_kernel<256><<<dim3(gnx, GY), 256, SM256>>>(
            hH, hL, w1H + (size_t)l * DD * FD, w1L + (size_t)l * DD * FD,
            b1 + (size_t)l * FD, nullptr, f1, FD, DD);
        gemm_bb_kernel<256><<<dim3(gnx, GY), 256, SM256>>>(
            hH, hL, w2H + (size_t)l * DD * FD, w2L + (size_t)l * DD * FD,
            b2 + (size_t)l * FD, nullptr, f2, FD, DD);

        silumul_split_kernel<<<(MM * (FD / 2)) / 256, 256>>>(f1, f2, f1H, f1L);

        gemm_bb_kernel<256><<<dim3(DD / 256, GY), 256, SM256>>>(
            f1H, f1L, w3H + (size_t)l * FD * DD, w3L + (size_t)l * FD * DD,
            b3 + (size_t)l * DD, x, x, DD, FD);
    }

    rmsnorm_split_kernel<<<MM, 256>>>(x, gpost, hH, hL);
    gemm_bb_kernel<256><<<dim3(VV / 256, GY), 256, SM256>>>(
        hH, hL, ebH, ebL, nullptr, nullptr, out, VV, DD);
}

// round 15
// speedup vs baseline: 1.2062x; 1.2062x over previous
#include <cuda_runtime.h>
#include <cuda_bf16.h>
#include <math.h>
#include <stdint.h>

// Problem dims (fixed by the dataset)
#define BB   2
#define SS   2048
#define DD   1024
#define HH   16
#define KVH  8
#define DK   64
#define FD   2752
#define NL   4
#define VV   32000
#define MM   (BB*SS)          // 4096 token rows
#define KVN  (KVH*DK)         // 512

// ---------------- scratch (device globals: no allocations allowed) ----------
__device__ float g_x [MM*DD];
__device__ float g_q [MM*DD];
__device__ float g_kv[MM*1024];
__device__ float g_f1[(size_t)MM*FD];
__device__ float g_f2[(size_t)MM*FD];
__device__ float g_bkv[NL*1024];

// split activations
__device__ __nv_bfloat16 g_hH [MM*DD],  g_hL [MM*DD];
__device__ __nv_bfloat16 g_oH [MM*DD],  g_oL [MM*DD];
__device__ __nv_bfloat16 g_kvH[MM*1024], g_kvL[MM*1024];
__device__ __nv_bfloat16 g_f1H[(size_t)MM*FD], g_f1L[(size_t)MM*FD];

// split transposed weights ([N][K] layout)
__device__ __nv_bfloat16 g_wqH [(size_t)NL*DD*DD],   g_wqL [(size_t)NL*DD*DD];
__device__ __nv_bfloat16 g_wkvH[(size_t)NL*1024*DD], g_wkvL[(size_t)NL*1024*DD];
__device__ __nv_bfloat16 g_woH [(size_t)NL*DD*DD],   g_woL [(size_t)NL*DD*DD];
__device__ __nv_bfloat16 g_w1H [(size_t)NL*DD*FD],   g_w1L [(size_t)NL*DD*FD];
__device__ __nv_bfloat16 g_w2H [(size_t)NL*DD*FD],   g_w2L [(size_t)NL*DD*FD];
__device__ __nv_bfloat16 g_w3H [(size_t)NL*FD*DD],   g_w3L [(size_t)NL*FD*DD];
__device__ __nv_bfloat16 g_ebH [(size_t)VV*DD],      g_ebL [(size_t)VV*DD];

// ---------------- bf16 split helper ----------------
__device__ __forceinline__ void split2(float x0, float x1,
                                       unsigned &hi, unsigned &lo) {
    __nv_bfloat162 h = __floats2bfloat162_rn(x0, x1);
    float h0 = __bfloat162float(h.x);
    float h1 = __bfloat162float(h.y);
    __nv_bfloat162 l = __floats2bfloat162_rn(x0 - h0, x1 - h1);
    hi = *reinterpret_cast<unsigned*>(&h);
    lo = *reinterpret_cast<unsigned*>(&l);
}

__device__ __forceinline__ unsigned smem_u32(const void* p) {
    unsigned r;
    asm("{ .reg .u64 t; cvta.to.shared.u64 t, %1; cvt.u32.u64 %0, t; }" : "=r"(r) : "l"(p));
    return r;
}

// ---------------- embedding gather ----------------
__global__ void embed_kernel(const int* __restrict__ tokens,
                             const float* __restrict__ emb,
                             float* __restrict__ x) {
    int row = blockIdx.x;
    int tok = tokens[row];
    const float4* src = (const float4*)(emb + (size_t)tok * DD);
    float4*       dst = (float4*)(x + (size_t)row * DD);
    dst[threadIdx.x] = src[threadIdx.x];
}

// ---------------- elementwise split (embed table) ----------------
__global__ void esplit_kernel(const float* __restrict__ W,
                              __nv_bfloat16* __restrict__ H,
                              __nv_bfloat16* __restrict__ L) {
    size_t i = ((size_t)blockIdx.x * 256 + threadIdx.x) * 4;
    float4 v = *(const float4*)(W + i);
    unsigned h0, l0, h1, l1;
    split2(v.x, v.y, h0, l0);
    split2(v.z, v.w, h1, l1);
    *(uint2*)(H + i) = make_uint2(h0, h1);
    *(uint2*)(L + i) = make_uint2(l0, l1);
}

// ---------------- transpose + split: W[K][N] -> H/L[N][K] ----------------
__global__ void tsplit_kernel(const float* __restrict__ W,
                              __nv_bfloat16* __restrict__ H,
                              __nv_bfloat16* __restrict__ L, int K, int N) {
    __shared__ float tile[32][33];
    int n0 = blockIdx.x * 32, k0 = blockIdx.y * 32;
    int tx = threadIdx.x, ty = threadIdx.y;
    #pragma unroll
    for (int i = 0; i < 32; i += 8)
        tile[ty + i][tx] = W[(size_t)(k0 + ty + i) * N + n0 + tx];
    __syncthreads();
    #pragma unroll
    for (int i = 0; i < 32; i += 8) {
        int n = n0 + ty + i, k = k0 + tx;
        float v = tile[tx][ty + i];
        __nv_bfloat16 h = __float2bfloat16_rn(v);
        H[(size_t)n * K + k] = h;
        L[(size_t)n * K + k] = __float2bfloat16_rn(v - __bfloat162float(h));
    }
}

// ---------------- bias concat for merged KV GEMM ----------------
__global__ void bkv_kernel(const float* __restrict__ bk, const float* __restrict__ bv,
                           float* __restrict__ bkv) {
    int l = blockIdx.x, t = threadIdx.x;
    bkv[l * 1024 + t]       = bk[l * 512 + t];
    bkv[l * 1024 + 512 + t] = bv[l * 512 + t];
}

// ---------------- rmsnorm -> split output ----------------
__global__ void rmsnorm_split_kernel(const float* __restrict__ x,
                                     const float* __restrict__ g,
                                     __nv_bfloat16* __restrict__ H,
                                     __nv_bfloat16* __restrict__ L) {
    int row = blockIdx.x;
    const float4* xr = (const float4*)(x + (size_t)row * DD);
    float4 v = xr[threadIdx.x];
    float ss = v.x*v.x + v.y*v.y + v.z*v.z + v.w*v.w;
    #pragma unroll
    for (int o = 16; o; o >>= 1) ss += __shfl_xor_sync(0xffffffffu, ss, o);
    __shared__ float red[8];
    if ((threadIdx.x & 31) == 0) red[threadIdx.x >> 5] = ss;
    __syncthreads();
    if (threadIdx.x < 8) {
        float r = red[threadIdx.x];
        #pragma unroll
        for (int o = 4; o; o >>= 1) r += __shfl_xor_sync(0xffu, r, o);
        if (threadIdx.x == 0) red[0] = r;
    }
    __syncthreads();
    float inv = rsqrtf(red[0] * (1.0f / DD) + 1e-6f);
    const float4* g4 = (const float4*)g;
    float4 gg = g4[threadIdx.x];
    float o0 = v.x*inv*gg.x, o1 = v.y*inv*gg.y, o2 = v.z*inv*gg.z, o3 = v.w*inv*gg.w;
    unsigned h0, l0, h1, l1;
    split2(o0, o1, h0, l0);
    split2(o2, o3, h1, l1);
    size_t base = (size_t)row * DD + threadIdx.x * 4;
    *(uint2*)(H + base) = make_uint2(h0, h1);
    *(uint2*)(L + base) = make_uint2(l0, l1);
}

// ---------------- kv: rope(k part) + split into bf16 hi/lo ----------------
__global__ void kvsplit_rope_kernel(const float* __restrict__ kv,
                                    const float* __restrict__ cosb,
                                    const float* __restrict__ sinb,
                                    __nv_bfloat16* __restrict__ H,
                                    __nv_bfloat16* __restrict__ L) {
    int row = blockIdx.x;
    int s   = row & (SS - 1);
    for (int pp = threadIdx.x; pp < 512; pp += 256) {
        int col = pp * 2;
        float2 v = *(const float2*)(kv + (size_t)row * 1024 + col);
        if (col < 512) {
            int p = (col & 63) >> 1;
            float c = cosb[s * 32 + p], sn = sinb[s * 32 + p];
            float xr = v.x, xi = v.y;
            v.x = xr * c - xi * sn;
            v.y = xr * sn + xi * c;
        }
        unsigned h_, l_;
        split2(v.x, v.y, h_, l_);
        ((unsigned*)H)[(size_t)row * 512 + pp] = h_;
        ((unsigned*)L)[(size_t)row * 512 + pp] = l_;
    }
}

#define BF16MMA(D, Ar, Br)                                                    \
    asm volatile(                                                             \
        "mma.sync.aligned.m16n8k16.row.col.f32.bf16.bf16.f32 "                \
        "{%0,%1,%2,%3}, {%4,%5,%6,%7}, {%8,%9}, {%0,%1,%2,%3};"               \
        : "+f"(D[0]), "+f"(D[1]), "+f"(D[2]), "+f"(D[3])                      \
        : "r"(Ar[0]), "r"(Ar[1]), "r"(Ar[2]), "r"(Ar[3]),                     \
          "r"(Br[0]), "r"(Br[1]))

#define LDSM4(R0, R1, R2, R3, ADDR)                                           \
    asm volatile("ldmatrix.sync.aligned.m8n8.x4.shared.b16 {%0,%1,%2,%3}, [%4];" \
        : "=r"(R0), "=r"(R1), "=r"(R2), "=r"(R3) : "r"(ADDR))

#define LDSM4T(R0, R1, R2, R3, ADDR)                                          \
    asm volatile("ldmatrix.sync.aligned.m8n8.x4.trans.shared.b16 {%0,%1,%2,%3}, [%4];" \
        : "=r"(R0), "=r"(R1), "=r"(R2), "=r"(R3) : "r"(ADDR))

// ======== flash attention v2: cp.async bf16 tiles + ldmatrix, 3x split =====
// rope(Q) fused into the Q-fragment load (frag pairs are rope pairs).
#define ARS 144
#define ATILE (64 * ARS)
#define ASTAGE (4 * ATILE)
#define ASMEM (2 * ASTAGE)        // 73728

__global__ __launch_bounds__(128)
void attn_tc_kernel(const float* __restrict__ Q,
                    const __nv_bfloat16* __restrict__ kvH,
                    const __nv_bfloat16* __restrict__ kvL,
                    const float* __restrict__ cosb, const float* __restrict__ sinb,
                    __nv_bfloat16* __restrict__ OH, __nv_bfloat16* __restrict__ OL) {
    extern __shared__ char asmem[];
    const unsigned sb0 = smem_u32(asmem);
    const int qb   = gridDim.x - 1 - blockIdx.x;   // heavy blocks first
    const int hd   = blockIdx.y;
    const int b    = blockIdx.z;
    const int kh   = hd >> 1;
    const int t    = threadIdx.x;
    const int lane = t & 31;
    const int w    = t >> 5;
    const int lq   = lane >> 2;
    const int lr   = lane & 3;

    // ---- resident Q fragments: load fp32, apply rope, scale, split ----
    unsigned qaH[4][4], qaL[4][4];
    {
        const int r0 = qb * 64 + w * 16 + lq;
        const int r1 = r0 + 8;
        const float* q0p = Q + ((size_t)(b * SS + r0) * HH + hd) * DK;
        const float* q1p = q0p + (size_t)8 * HH * DK;
        #pragma unroll
        for (int kb = 0; kb < 4; kb++) {
            int p0 = kb * 8 + lr, p1 = kb * 8 + 4 + lr;
            float c00 = cosb[r0 * 32 + p0], s00 = sinb[r0 * 32 + p0];
            float c10 = cosb[r1 * 32 + p0], s10 = sinb[r1 * 32 + p0];
            float c01 = cosb[r0 * 32 + p1], s01 = sinb[r0 * 32 + p1];
            float c11 = cosb[r1 * 32 + p1], s11 = sinb[r1 * 32 + p1];
            float2 v0 = *(const float2*)(q0p + kb * 16 + 2 * lr);
            float2 v1 = *(const float2*)(q1p + kb * 16 + 2 * lr);
            float2 v2 = *(const float2*)(q0p + kb * 16 + 8 + 2 * lr);
            float2 v3 = *(const float2*)(q1p + kb * 16 + 8 + 2 * lr);
            float a0 = v0.x * c00 - v0.y * s00, b0 = v0.x * s00 + v0.y * c00;
            float a1 = v1.x * c10 - v1.y * s10, b1 = v1.x * s10 + v1.y * c10;
            float a2 = v2.x * c01 - v2.y * s01, b2 = v2.x * s01 + v2.y * c01;
            float a3 = v3.x * c11 - v3.y * s11, b3 = v3.x * s11 + v3.y * c11;
            split2(a0 * 0.125f, b0 * 0.125f, qaH[kb][0], qaL[kb][0]);
            split2(a1 * 0.125f, b1 * 0.125f, qaH[kb][1], qaL[kb][1]);
            split2(a2 * 0.125f, b2 * 0.125f, qaH[kb][2], qaL[kb][2]);
            split2(a3 * 0.125f, b3 * 0.125f, qaH[kb][3], qaL[kb][3]);
        }
    }

    float acc[8][4] = {};
    float m0 = -1e30f, m1 = -1e30f, l0 = 0.f, l1 = 0.f;
    const int ntiles = qb + 1;

    const unsigned aOff = (unsigned)(lane & 15) * ARS + (unsigned)(lane >> 4) * 16;
    const unsigned bOff = (unsigned)((lane >> 4) * 8 + (lane & 7)) * ARS
                        + (unsigned)((lane >> 3) & 1) * 16;

    auto issue_tile = [&](int kt) {
        const int kbase = kt * 64;
        unsigned sb = sb0 + (kt & 1) * ASTAGE;
        #pragma unroll
        for (int i = 0; i < 16; i++) {
            int c   = t + i * 128;
            int buf = c >> 9;
            int cc  = c & 511;
            int row = cc >> 3, q8 = cc & 7;
            const __nv_bfloat16* bp = (buf & 1) ? kvL : kvH;
            int voff = (buf >> 1) * 512;
            const __nv_bfloat16* src = bp + (size_t)(b * SS + kbase + row) * 1024
                                          + voff + kh * 64 + q8 * 8;
            unsigned dst = sb + buf * ATILE + row * ARS + q8 * 16;
            asm volatile("cp.async.cg.shared.global [%0], [%1], 16;"
                         :: "r"(dst), "l"(src) : "memory");
        }
        asm volatile("cp.async.commit_group;" ::: "memory");
    };

    issue_tile(0);
    for (int kt = 0; kt < ntiles; kt++) {
        if (kt + 1 < ntiles) {
            issue_tile(kt + 1);
            asm volatile("cp.async.wait_group 1;" ::: "memory");
        } else {
            asm volatile("cp.async.wait_group 0;" ::: "memory");
        }
        __syncthreads();

        const unsigned stb = sb0 + (kt & 1) * ASTAGE;
        const int kbase = kt * 64;

        float s[8][4] = {};
        #pragma unroll
        for (int kb = 0; kb < 4; kb++) {
            unsigned kfH[4][4], kfL[4][4];
            #pragma unroll
            for (int ng = 0; ng < 4; ng++) {
                unsigned ad = stb + (unsigned)(ng * 16) * ARS + kb * 32 + bOff;
                LDSM4(kfH[ng][0], kfH[ng][1], kfH[ng][2], kfH[ng][3], ad);
                LDSM4(kfL[ng][0], kfL[ng][1], kfL[ng][2], kfL[ng][3], ad + ATILE);
            }
            #pragma unroll
            for (int ng = 0; ng < 4; ng++) {
                BF16MMA(s[ng*2],   qaH[kb], (kfH[ng] + 0));
                BF16MMA(s[ng*2],   qaL[kb], (kfH[ng] + 0));
                BF16MMA(s[ng*2],   qaH[kb], (kfL[ng] + 0));
                BF16MMA(s[ng*2+1], qaH[kb], (kfH[ng] + 2));
                BF16MMA(s[ng*2+1], qaL[kb], (kfH[ng] + 2));
                BF16MMA(s[ng*2+1], qaH[kb], (kfL[ng] + 2));
            }
        }

        if (kt == qb) {
            int row0 = qb * 64 + w * 16 + lq;
            #pragma unroll
            for (int ni = 0; ni < 8; ni++) {
                int col = kbase + ni * 8 + 2 * lr;
                if (col     > row0)     s[ni][0] = -1e30f;
                if (col + 1 > row0)     s[ni][1] = -1e30f;
                if (col     > row0 + 8) s[ni][2] = -1e30f;
                if (col + 1 > row0 + 8) s[ni][3] = -1e30f;
            }
        }

        float mt0 = -1e30f, mt1 = -1e30f;
        #pragma unroll
        for (int ni = 0; ni < 8; ni++) {
            mt0 = fmaxf(mt0, fmaxf(s[ni][0], s[ni][1]));
            mt1 = fmaxf(mt1, fmaxf(s[ni][2], s[ni][3]));
        }
        mt0 = fmaxf(mt0, __shfl_xor_sync(0xffffffffu, mt0, 1));
        mt0 = fmaxf(mt0, __shfl_xor_sync(0xffffffffu, mt0, 2));
        mt1 = fmaxf(mt1, __shfl_xor_sync(0xffffffffu, mt1, 1));
        mt1 = fmaxf(mt1, __shfl_xor_sync(0xffffffffu, mt1, 2));
        float mn0 = fmaxf(m0, mt0), mn1 = fmaxf(m1, mt1);
        float c0 = __expf(m0 - mn0), c1 = __expf(m1 - mn1);
        m0 = mn0; m1 = mn1;
        float rs0 = 0.f, rs1 = 0.f;
        #pragma unroll
        for (int ni = 0; ni < 8; ni++) {
            s[ni][0] = __expf(s[ni][0] - mn0);
            s[ni][1] = __expf(s[ni][1] - mn0);
            s[ni][2] = __expf(s[ni][2] - mn1);
            s[ni][3] = __expf(s[ni][3] - mn1);
            rs0 += s[ni][0] + s[ni][1];
            rs1 += s[ni][2] + s[ni][3];
        }
        rs0 += __shfl_xor_sync(0xffffffffu, rs0, 1);
        rs0 += __shfl_xor_sync(0xffffffffu, rs0, 2);
        rs1 += __shfl_xor_sync(0xffffffffu, rs1, 1);
        rs1 += __shfl_xor_sync(0xffffffffu, rs1, 2);
        l0 = l0 * c0 + rs0;
        l1 = l1 * c1 + rs1;
        #pragma unroll
        for (int dn = 0; dn < 8; dn++) {
            acc[dn][0] *= c0; acc[dn][1] *= c0;
            acc[dn][2] *= c1; acc[dn][3] *= c1;
        }

        #pragma unroll
        for (int kb = 0; kb < 4; kb++) {
            unsigned aPH[4], aPL[4];
            split2(s[2*kb][0],   s[2*kb][1],   aPH[0], aPL[0]);
            split2(s[2*kb][2],   s[2*kb][3],   aPH[1], aPL[1]);
            split2(s[2*kb+1][0], s[2*kb+1][1], aPH[2], aPL[2]);
            split2(s[2*kb+1][2], s[2*kb+1][3], aPH[3], aPL[3]);
            #pragma unroll
            for (int dn = 0; dn < 4; dn++) {
                unsigned vfH[4], vfL[4];
                unsigned ad = stb + 2 * ATILE + (unsigned)(kb * 16) * ARS
                            + (unsigned)(dn * 16) * 2 + aOff;
                LDSM4T(vfH[0], vfH[1], vfH[2], vfH[3], ad);
                LDSM4T(vfL[0], vfL[1], vfL[2], vfL[3], ad + ATILE);
                float* acc0 = acc[dn * 2];
                float* acc1 = acc[dn * 2 + 1];
                BF16MMA(acc0, aPH, (vfH + 0));
                BF16MMA(acc0, aPL, (vfH + 0));
                BF16MMA(acc0, aPH, (vfL + 0));
                BF16MMA(acc1, aPH, (vfH + 2));
                BF16MMA(acc1, aPL, (vfH + 2));
                BF16MMA(acc1, aPH, (vfL + 2));
            }
        }
        __syncthreads();
    }

    float inv0 = 1.f / l0, inv1 = 1.f / l1;
    int row0 = qb * 64 + w * 16 + lq;
    size_t b0 = ((size_t)(b * SS + row0) * HH + hd) * DK;
    size_t b1 = b0 + (size_t)8 * HH * DK;
    #pragma unroll
    for (int dn = 0; dn < 8; dn++) {
        int d = dn * 8 + 2 * lr;
        unsigned h_, l_;
        split2(acc[dn][0] * inv0, acc[dn][1] * inv0, h_, l_);
        *(unsigned*)(OH + b0 + d) = h_;
        *(unsigned*)(OL + b0 + d) = l_;
        split2(acc[dn][2] * inv1, acc[dn][3] * inv1, h_, l_);
        *(unsigned*)(OH + b1 + d) = h_;
        *(unsigned*)(OL + b1 + d) = l_;
    }
}

// ========== pure-bf16 split GEMM, cp.async 3-stage, ldmatrix (R12) =========
#define G_BK 32
#define G_RS 80

template<int BN>
__global__ __launch_bounds__(256)
void gemm_bb_kernel(const __nv_bfloat16* __restrict__ AH_, const __nv_bfloat16* __restrict__ AL_,
                    const __nv_bfloat16* __restrict__ BH_, const __nv_bfloat16* __restrict__ BL_,
                    const float* __restrict__ bias, const float* __restrict__ res,
                    float* __restrict__ C, int Nd, int Kd) {
    constexpr int NG      = BN / 64;
    constexpr unsigned OFF_AL = 128 * G_RS;
    constexpr unsigned OFF_BH = 256 * G_RS;
    constexpr unsigned OFF_BL = (256 + BN) * G_RS;
    constexpr unsigned STAGE  = (256 + 2 * BN) * G_RS;
    constexpr int CH_B    = BN * 4;

    extern __shared__ char smem[];
    const unsigned sbase = smem_u32(smem);
    const int t    = threadIdx.x;
    const int lane = t & 31;
    const int warp = t >> 5;
    const int wm   = warp >> 2;
    const int wn   = warp & 3;
    const int bm   = blockIdx.y * 128;
    const int bn   = blockIdx.x * BN;

    float acc[4][2 * NG][4] = {};
    const int nkt = Kd / G_BK;

    auto issue_stage = [&](int kt) {
        const int k0 = kt * G_BK;
        unsigned sb = sbase + (kt % 3) * STAGE;
        #pragma unroll
        for (int i = 0; i < 4; i++) {
            int c = t + i * 256;
            const __nv_bfloat16* base = (c < 512) ? AH_ : AL_;
            unsigned offt = (c < 512) ? 0u : OFF_AL;
            int cc = c & 511;
            int row = cc >> 2, quad = cc & 3;
            const __nv_bfloat16* src = base + (size_t)(bm + row) * Kd + k0 + quad * 8;
            unsigned dst = sb + offt + row * G_RS + quad * 16;
            asm volatile("cp.async.cg.shared.global [%0], [%1], 16;"
                         :: "r"(dst), "l"(src) : "memory");
        }
        #pragma unroll
        for (int i = 0; i < BN / 32; i++) {
            int c = t + i * 256;
            const __nv_bfloat16* base = (c < CH_B) ? BH_ : BL_;
            unsigned offt = (c < CH_B) ? OFF_BH : OFF_BL;
            int cc = c & (CH_B - 1);
            int row = cc >> 2, quad = cc & 3;
            const __nv_bfloat16* src = base + (size_t)(bn + row) * Kd + k0 + quad * 8;
            unsigned dst = sb + offt + row * G_RS + quad * 16;
            int vsz = (bn + row < Nd) ? 16 : 0;
            asm volatile("cp.async.cg.shared.global [%0], [%1], 16, %2;"
                         :: "r"(dst), "l"(src), "r"(vsz) : "memory");
        }
        asm volatile("cp.async.commit_group;" ::: "memory");
    };

    issue_stage(0);
    issue_stage(1);

    const int m0 = wm * 64;
    const int n0 = wn * (BN / 4);
    const int lq = lane >> 2;
    const int lr = lane & 3;
    const unsigned aRowOff = (unsigned)(lane & 15) * G_RS + (unsigned)(lane >> 4) * 16;
    const unsigned bRowOff = ((unsigned)((lane >> 4) * 8 + (lane & 7))) * G_RS
                           + (unsigned)((lane >> 3) & 1) * 16;

    for (int kt = 0; kt < nkt; kt++) {
        asm volatile("cp.async.wait_group 1;" ::: "memory");
        __syncthreads();
        if (kt + 2 < nkt) issue_stage(kt + 2);
        else asm volatile("cp.async.commit_group;" ::: "memory");

        const unsigned stb = sbase + (kt % 3) * STAGE;
        #pragma unroll
        for (int ks = 0; ks < 2; ks++) {
            unsigned aH[4][4], aL[4][4], bH[NG][4], bL[NG][4];
            const unsigned ksb = ks * 32;
            #pragma unroll
            for (int mi = 0; mi < 4; mi++) {
                unsigned ah = stb + (m0 + mi * 16) * G_RS + ksb + aRowOff;
                unsigned al = ah + OFF_AL;
                LDSM4(aH[mi][0], aH[mi][1], aH[mi][2], aH[mi][3], ah);
                LDSM4(aL[mi][0], aL[mi][1], aL[mi][2], aL[mi][3], al);
            }
            #pragma unroll
            for (int ng = 0; ng < NG; ng++) {
                unsigned bhh = stb + OFF_BH + (n0 + ng * 16) * G_RS + ksb + bRowOff;
                unsigned bll = bhh + (unsigned)(BN * G_RS);
                LDSM4(bH[ng][0], bH[ng][1], bH[ng][2], bH[ng][3], bhh);
                LDSM4(bL[ng][0], bL[ng][1], bL[ng][2], bL[ng][3], bll);
            }
            #pragma unroll
            for (int mi = 0; mi < 4; mi++)
                #pragma unroll
                for (int ng = 0; ng < NG; ng++) {
                    float* acc0 = acc[mi][ng * 2];
                    float* acc1 = acc[mi][ng * 2 + 1];
                    BF16MMA(acc0, aH[mi], (bH[ng] + 0));
                    BF16MMA(acc0, aL[mi], (bH[ng] + 0));
                    BF16MMA(acc0, aH[mi], (bL[ng] + 0));
                    BF16MMA(acc1, aH[mi], (bH[ng] + 2));
                    BF16MMA(acc1, aL[mi], (bH[ng] + 2));
                    BF16MMA(acc1, aH[mi], (bL[ng] + 2));
                }
        }
    }

    #pragma unroll
    for (int mi = 0; mi < 4; mi++) {
        int row = bm + m0 + mi * 16 + lq;
        #pragma unroll
        for (int ni = 0; ni < 2 * NG; ni++) {
            int col = bn + n0 + ni * 8 + lr * 2;
            if (col < Nd) {
                float v0 = acc[mi][ni][0], v1 = acc[mi][ni][1];
                float v2 = acc[mi][ni][2], v3 = acc[mi][ni][3];
                if (bias) {
                    float bx = bias[col], by = bias[col + 1];
                    v0 += bx; v1 += by; v2 += bx; v3 += by;
                }
                size_t o0 = (size_t)row * Nd + col;
                size_t o1 = (size_t)(row + 8) * Nd + col;
                if (res) {
                    v0 += res[o0]; v1 += res[o0 + 1];
                    v2 += res[o1]; v3 += res[o1 + 1];
                }
                C[o0] = v0; C[o0 + 1] = v1;
                C[o1] = v2; C[o1 + 1] = v3;
            }
        }
    }
}

#define SM128 ((256 + 2 * 128) * G_RS * 3)    // 122880
#define SM256 ((256 + 2 * 256) * G_RS * 3)    // 184320

// ---------------- silu(f1)*f2 -> split ----------------
__global__ void silumul_split_kernel(const float* __restrict__ f1,
                                     const float* __restrict__ f2,
                                     __nv_bfloat16* __restrict__ H,
                                     __nv_bfloat16* __restrict__ L) {
    size_t i = (size_t)blockIdx.x * 256 + threadIdx.x;
    float2 a = ((const float2*)f1)[i];
    float2 b = ((const float2*)f2)[i];
    float g0 = a.x / (1.0f + __expf(-a.x)) * b.x;
    float g1 = a.y / (1.0f + __expf(-a.y)) * b.y;
    unsigned h_, l_;
    split2(g0, g1, h_, l_);
    ((unsigned*)H)[i] = h_;
    ((unsigned*)L)[i] = l_;
}

// ---------------- host driver ----------------
extern "C" void kernel_launch(void* const* d_in, const int* in_sizes, int n_in,
                              void* d_out, int out_size) {
    const int*   tokens = (const int*)  d_in[0];
    const float* emb    = (const float*)d_in[1];
    const float* wq = (const float*)d_in[2];
    const float* bq = (const float*)d_in[3];
    const float* wk = (const float*)d_in[4];
    const float* bk = (const float*)d_in[5];
    const float* wv = (const float*)d_in[6];
    const float* bv = (const float*)d_in[7];
    const float* wo = (const float*)d_in[8];
    const float* bo = (const float*)d_in[9];
    const float* w1 = (const float*)d_in[10];
    const float* b1 = (const float*)d_in[11];
    const float* w2 = (const float*)d_in[12];
    const float* b2 = (const float*)d_in[13];
    const float* w3 = (const float*)d_in[14];
    const float* b3 = (const float*)d_in[15];
    const float* g1 = (const float*)d_in[16];
    const float* g2 = (const float*)d_in[17];
    const float* gpost = (const float*)d_in[18];
    const float* fcos  = (const float*)d_in[19];
    const float* fsin  = (const float*)d_in[20];
    float* out = (float*)d_out;

    float *x, *q, *kv, *f1, *f2, *bkv;
    __nv_bfloat16 *hH, *hL, *oH, *oL, *kvH, *kvL, *f1H, *f1L;
    __nv_bfloat16 *wqH, *wqL, *wkvH, *wkvL, *woH, *woL;
    __nv_bfloat16 *w1H, *w1L, *w2H, *w2L, *w3H, *w3L, *ebH, *ebL;
    cudaGetSymbolAddress((void**)&x,   g_x);
    cudaGetSymbolAddress((void**)&q,   g_q);
    cudaGetSymbolAddress((void**)&kv,  g_kv);
    cudaGetSymbolAddress((void**)&f1,  g_f1);
    cudaGetSymbolAddress((void**)&f2,  g_f2);
    cudaGetSymbolAddress((void**)&bkv, g_bkv);
    cudaGetSymbolAddress((void**)&hH,  g_hH);   cudaGetSymbolAddress((void**)&hL,  g_hL);
    cudaGetSymbolAddress((void**)&oH,  g_oH);   cudaGetSymbolAddress((void**)&oL,  g_oL);
    cudaGetSymbolAddress((void**)&kvH, g_kvH);  cudaGetSymbolAddress((void**)&kvL, g_kvL);
    cudaGetSymbolAddress((void**)&f1H, g_f1H);  cudaGetSymbolAddress((void**)&f1L, g_f1L);
    cudaGetSymbolAddress((void**)&wqH, g_wqH);  cudaGetSymbolAddress((void**)&wqL, g_wqL);
    cudaGetSymbolAddress((void**)&wkvH, g_wkvH); cudaGetSymbolAddress((void**)&wkvL, g_wkvL);
    cudaGetSymbolAddress((void**)&woH, g_woH);  cudaGetSymbolAddress((void**)&woL, g_woL);
    cudaGetSymbolAddress((void**)&w1H, g_w1H);  cudaGetSymbolAddress((void**)&w1L, g_w1L);
    cudaGetSymbolAddress((void**)&w2H, g_w2H);  cudaGetSymbolAddress((void**)&w2L, g_w2L);
    cudaGetSymbolAddress((void**)&w3H, g_w3H);  cudaGetSymbolAddress((void**)&w3L, g_w3L);
    cudaGetSymbolAddress((void**)&ebH, g_ebH);  cudaGetSymbolAddress((void**)&ebL, g_ebL);

    cudaFuncSetAttribute(gemm_bb_kernel<128>,
                         cudaFuncAttributeMaxDynamicSharedMemorySize, SM128);
    cudaFuncSetAttribute(gemm_bb_kernel<256>,
                         cudaFuncAttributeMaxDynamicSharedMemorySize, SM256);
    cudaFuncSetAttribute(attn_tc_kernel,
                         cudaFuncAttributeMaxDynamicSharedMemorySize, ASMEM);

    // ---- conversions (inside graph) ----
    esplit_kernel<<<(VV * DD) / (256 * 4), 256>>>(emb, ebH, ebL);
    bkv_kernel<<<NL, 512>>>(bk, bv, bkv);
    dim3 tb(32, 8);
    for (int l = 0; l < NL; l++) {
        tsplit_kernel<<<dim3(DD / 32, DD / 32), tb>>>(
            wq + (size_t)l * DD * DD, wqH + (size_t)l * DD * DD, wqL + (size_t)l * DD * DD, DD, DD);
        tsplit_kernel<<<dim3(KVN / 32, DD / 32), tb>>>(
            wk + (size_t)l * DD * KVN,
            wkvH + (size_t)l * 1024 * DD, wkvL + (size_t)l * 1024 * DD, DD, KVN);
        tsplit_kernel<<<dim3(KVN / 32, DD / 32), tb>>>(
            wv + (size_t)l * DD * KVN,
            wkvH + (size_t)l * 1024 * DD + (size_t)512 * DD,
            wkvL + (size_t)l * 1024 * DD + (size_t)512 * DD, DD, KVN);
        tsplit_kernel<<<dim3(DD / 32, DD / 32), tb>>>(
            wo + (size_t)l * DD * DD, woH + (size_t)l * DD * DD, woL + (size_t)l * DD * DD, DD, DD);
        tsplit_kernel<<<dim3(FD / 32, DD / 32), tb>>>(
            w1 + (size_t)l * DD * FD, w1H + (size_t)l * DD * FD, w1L + (size_t)l * DD * FD, DD, FD);
        tsplit_kernel<<<dim3(FD / 32, DD / 32), tb>>>(
            w2 + (size_t)l * DD * FD, w2H + (size_t)l * DD * FD, w2L + (size_t)l * DD * FD, DD, FD);
        tsplit_kernel<<<dim3(DD / 32, FD / 32), tb>>>(
            w3 + (size_t)l * FD * DD, w3H + (size_t)l * FD * DD, w3L + (size_t)l * FD * DD, FD, DD);
    }

    embed_kernel<<<MM, 256>>>(tokens, emb, x);

    const int GY = MM / 128;    // 32
    for (int l = 0; l < NL; l++) {
        rmsnorm_split_kernel<<<MM, 256>>>(x, g1 + (size_t)l * DD, hH, hL);

        gemm_bb_kernel<256><<<dim3(DD / 256, GY), 256, SM256>>>(
            hH, hL, wqH + (size_t)l * DD * DD, wqL + (size_t)l * DD * DD,
            bq + (size_t)l * DD, nullptr, q, DD, DD);
        gemm_bb_kernel<256><<<dim3(1024 / 256, GY), 256, SM256>>>(
            hH, hL, wkvH + (size_t)l * 1024 * DD, wkvL + (size_t)l * 1024 * DD,
            bkv + (size_t)l * 1024, nullptr, kv, 1024, DD);

        kvsplit_rope_kernel<<<MM, 256>>>(kv, fcos, fsin, kvH, kvL);

        attn_tc_kernel<<<dim3(SS / 64, HH, BB), 128, ASMEM>>>(
            q, kvH, kvL, fcos, fsin, oH, oL);

        gemm_bb_kernel<256><<<dim3(DD / 256, GY), 256, SM256>>>(
            oH, oL, woH + (size_t)l * DD * DD, woL + (size_t)l * DD * DD,
            bo + (size_t)l * DD, x, x, DD, DD);

        rmsnorm_split_kernel<<<MM, 256>>>(x, g2 + (size_t)l * DD, hH, hL);

        int gnx = (FD + 255) / 256;   // 11
        gemm_bb_kernel<256><<<dim3(gnx, GY), 256, SM256>>>(
            hH, hL, w1H + (size_t)l * DD * FD, w1L + (size_t)l * DD * FD,
            b1 + (size_t)l * FD, nullptr, f1, FD, DD);
        gemm_bb_kernel<256><<<dim3(gnx, GY), 256, SM256>>>(
            hH, hL, w2H + (size_t)l * DD * FD, w2L + (size_t)l * DD * FD,
            b2 + (size_t)l * FD, nullptr, f2, FD, DD);

        silumul_split_kernel<<<(MM * (FD / 2)) / 256, 256>>>(f1, f2, f1H, f1L);

        gemm_bb_kernel<256><<<dim3(DD / 256, GY), 256, SM256>>>(
            f1H, f1L, w3H + (size_t)l * FD * DD, w3L + (size_t)l * FD * DD,
            b3 + (size_t)l * DD, x, x, DD, FD);
    }

    rmsnorm_split_kernel<<<MM, 256>>>(x, gpost, hH, hL);
    gemm_bb_kernel<256><<<dim3(VV / 256, GY), 256, SM256>>>(
        hH, hL, ebH, ebL, nullptr, nullptr, out, VV, DD);
}

// round 16
// speedup vs baseline: 1.6956x; 1.4058x over previous
#include <cuda_runtime.h>
#include <cuda_fp16.h>
#include <math.h>
#include <stdint.h>

// Problem dims (fixed by the dataset)
#define BB   2
#define SS   2048
#define DD   1024
#define HH   16
#define KVH  8
#define DK   64
#define FD   2752
#define NL   4
#define VV   32000
#define MM   (BB*SS)          // 4096 token rows
#define KVN  (KVH*DK)         // 512

// ---------------- scratch (device globals: no allocations allowed) ----------
__device__ float g_x [MM*DD];
__device__ float g_q [MM*DD];
__device__ float g_kv[MM*1024];
__device__ float g_f1[(size_t)MM*FD];
__device__ float g_f2[(size_t)MM*FD];
__device__ float g_bkv[NL*1024];

// split activations (fp16 hi/lo)
__device__ __half g_hH [MM*DD],  g_hL [MM*DD];
__device__ __half g_oH [MM*DD],  g_oL [MM*DD];
__device__ __half g_kvh[MM*1024];
__device__ __half g_f1H[(size_t)MM*FD], g_f1L[(size_t)MM*FD];

// fp16 transposed weights ([N][K] layout, hi only)
__device__ __half g_wq [(size_t)NL*DD*DD];
__device__ __half g_wkv[(size_t)NL*1024*DD];
__device__ __half g_wo [(size_t)NL*DD*DD];
__device__ __half g_w1 [(size_t)NL*DD*FD];
__device__ __half g_w2 [(size_t)NL*DD*FD];
__device__ __half g_w3 [(size_t)NL*FD*DD];
__device__ __half g_eb [(size_t)VV*DD];

// ---------------- fp16 split helper ----------------
__device__ __forceinline__ void split2(float x0, float x1,
                                       unsigned &hi, unsigned &lo) {
    __half2 h = __floats2half2_rn(x0, x1);
    float2 hf = __half22float2(h);
    __half2 l = __floats2half2_rn(x0 - hf.x, x1 - hf.y);
    hi = *reinterpret_cast<unsigned*>(&h);
    lo = *reinterpret_cast<unsigned*>(&l);
}

__device__ __forceinline__ unsigned smem_u32(const void* p) {
    unsigned r;
    asm("{ .reg .u64 t; cvta.to.shared.u64 t, %1; cvt.u32.u64 %0, t; }" : "=r"(r) : "l"(p));
    return r;
}

// ---------------- embedding gather ----------------
__global__ void embed_kernel(const int* __restrict__ tokens,
                             const float* __restrict__ emb,
                             float* __restrict__ x) {
    int row = blockIdx.x;
    int tok = tokens[row];
    const float4* src = (const float4*)(emb + (size_t)tok * DD);
    float4*       dst = (float4*)(x + (size_t)row * DD);
    dst[threadIdx.x] = src[threadIdx.x];
}

// ---------------- elementwise fp16 convert (embed table) ----------------
__global__ void esplit_kernel(const float* __restrict__ W,
                              __half* __restrict__ H) {
    size_t i = ((size_t)blockIdx.x * 256 + threadIdx.x) * 4;
    float4 v = *(const float4*)(W + i);
    __half2 h0 = __floats2half2_rn(v.x, v.y);
    __half2 h1 = __floats2half2_rn(v.z, v.w);
    *(uint2*)(H + i) = make_uint2(*(unsigned*)&h0, *(unsigned*)&h1);
}

// ---------------- transpose + convert: W[K][N] -> H[N][K] fp16 ----------------
__global__ void tsplit_kernel(const float* __restrict__ W,
                              __half* __restrict__ H, int K, int N) {
    __shared__ float tile[32][33];
    int n0 = blockIdx.x * 32, k0 = blockIdx.y * 32;
    int tx = threadIdx.x, ty = threadIdx.y;
    #pragma unroll
    for (int i = 0; i < 32; i += 8)
        tile[ty + i][tx] = W[(size_t)(k0 + ty + i) * N + n0 + tx];
    __syncthreads();
    #pragma unroll
    for (int i = 0; i < 32; i += 8) {
        int n = n0 + ty + i, k = k0 + tx;
        H[(size_t)n * K + k] = __float2half_rn(tile[tx][ty + i]);
    }
}

// ---------------- bias concat for merged KV GEMM ----------------
__global__ void bkv_kernel(const float* __restrict__ bk, const float* __restrict__ bv,
                           float* __restrict__ bkv) {
    int l = blockIdx.x, t = threadIdx.x;
    bkv[l * 1024 + t]       = bk[l * 512 + t];
    bkv[l * 1024 + 512 + t] = bv[l * 512 + t];
}

// ---------------- rmsnorm -> split output ----------------
__global__ void rmsnorm_split_kernel(const float* __restrict__ x,
                                     const float* __restrict__ g,
                                     __half* __restrict__ H,
                                     __half* __restrict__ L) {
    int row = blockIdx.x;
    const float4* xr = (const float4*)(x + (size_t)row * DD);
    float4 v = xr[threadIdx.x];
    float ss = v.x*v.x + v.y*v.y + v.z*v.z + v.w*v.w;
    #pragma unroll
    for (int o = 16; o; o >>= 1) ss += __shfl_xor_sync(0xffffffffu, ss, o);
    __shared__ float red[8];
    if ((threadIdx.x & 31) == 0) red[threadIdx.x >> 5] = ss;
    __syncthreads();
    if (threadIdx.x < 8) {
        float r = red[threadIdx.x];
        #pragma unroll
        for (int o = 4; o; o >>= 1) r += __shfl_xor_sync(0xffu, r, o);
        if (threadIdx.x == 0) red[0] = r;
    }
    __syncthreads();
    float inv = rsqrtf(red[0] * (1.0f / DD) + 1e-6f);
    const float4* g4 = (const float4*)g;
    float4 gg = g4[threadIdx.x];
    float o0 = v.x*inv*gg.x, o1 = v.y*inv*gg.y, o2 = v.z*inv*gg.z, o3 = v.w*inv*gg.w;
    unsigned h0, l0, h1, l1;
    split2(o0, o1, h0, l0);
    split2(o2, o3, h1, l1);
    size_t base = (size_t)row * DD + threadIdx.x * 4;
    *(uint2*)(H + base) = make_uint2(h0, h1);
    *(uint2*)(L + base) = make_uint2(l0, l1);
}

// ---------------- kv: rope(k part) + fp16 convert ----------------
__global__ void kvsplit_rope_kernel(const float* __restrict__ kv,
                                    const float* __restrict__ cosb,
                                    const float* __restrict__ sinb,
                                    __half* __restrict__ H) {
    int row = blockIdx.x;
    int s   = row & (SS - 1);
    for (int pp = threadIdx.x; pp < 512; pp += 256) {
        int col = pp * 2;
        float2 v = *(const float2*)(kv + (size_t)row * 1024 + col);
        if (col < 512) {
            int p = (col & 63) >> 1;
            float c = cosb[s * 32 + p], sn = sinb[s * 32 + p];
            float xr = v.x, xi = v.y;
            v.x = xr * c - xi * sn;
            v.y = xr * sn + xi * c;
        }
        __half2 h = __floats2half2_rn(v.x, v.y);
        ((unsigned*)H)[(size_t)row * 512 + pp] = *(unsigned*)&h;
    }
}

#define F16MMA(D, Ar, Br)                                                     \
    asm volatile(                                                             \
        "mma.sync.aligned.m16n8k16.row.col.f32.f16.f16.f32 "                  \
        "{%0,%1,%2,%3}, {%4,%5,%6,%7}, {%8,%9}, {%0,%1,%2,%3};"               \
        : "+f"(D[0]), "+f"(D[1]), "+f"(D[2]), "+f"(D[3])                      \
        : "r"(Ar[0]), "r"(Ar[1]), "r"(Ar[2]), "r"(Ar[3]),                     \
          "r"(Br[0]), "r"(Br[1]))

#define LDSM4(R0, R1, R2, R3, ADDR)                                           \
    asm volatile("ldmatrix.sync.aligned.m8n8.x4.shared.b16 {%0,%1,%2,%3}, [%4];" \
        : "=r"(R0), "=r"(R1), "=r"(R2), "=r"(R3) : "r"(ADDR))

#define LDSM4T(R0, R1, R2, R3, ADDR)                                          \
    asm volatile("ldmatrix.sync.aligned.m8n8.x4.trans.shared.b16 {%0,%1,%2,%3}, [%4];" \
        : "=r"(R0), "=r"(R1), "=r"(R2), "=r"(R3) : "r"(ADDR))

// ======== flash attention v2: fp16 K/V, compensated Q/P (2-MMA) ===========
#define ARS 144
#define ATILE (64 * ARS)
#define ASTAGE (2 * ATILE)        // K tile + V tile
#define ASMEM (2 * ASTAGE)        // 36864

__global__ __launch_bounds__(128)
void attn_tc_kernel(const float* __restrict__ Q,
                    const __half* __restrict__ kvh,
                    const float* __restrict__ cosb, const float* __restrict__ sinb,
                    __half* __restrict__ OH, __half* __restrict__ OL) {
    extern __shared__ char asmem[];
    const unsigned sb0 = smem_u32(asmem);
    const int qb   = gridDim.x - 1 - blockIdx.x;   // heavy blocks first
    const int hd   = blockIdx.y;
    const int b    = blockIdx.z;
    const int kh   = hd >> 1;
    const int t    = threadIdx.x;
    const int lane = t & 31;
    const int w    = t >> 5;
    const int lq   = lane >> 2;
    const int lr   = lane & 3;

    // ---- resident Q fragments: load fp32, rope, scale, split ----
    unsigned qaH[4][4], qaL[4][4];
    {
        const int r0 = qb * 64 + w * 16 + lq;
        const int r1 = r0 + 8;
        const float* q0p = Q + ((size_t)(b * SS + r0) * HH + hd) * DK;
        const float* q1p = q0p + (size_t)8 * HH * DK;
        #pragma unroll
        for (int kb = 0; kb < 4; kb++) {
            int p0 = kb * 8 + lr, p1 = kb * 8 + 4 + lr;
            float c00 = cosb[r0 * 32 + p0], s00 = sinb[r0 * 32 + p0];
            float c10 = cosb[r1 * 32 + p0], s10 = sinb[r1 * 32 + p0];
            float c01 = cosb[r0 * 32 + p1], s01 = sinb[r0 * 32 + p1];
            float c11 = cosb[r1 * 32 + p1], s11 = sinb[r1 * 32 + p1];
            float2 v0 = *(const float2*)(q0p + kb * 16 + 2 * lr);
            float2 v1 = *(const float2*)(q1p + kb * 16 + 2 * lr);
            float2 v2 = *(const float2*)(q0p + kb * 16 + 8 + 2 * lr);
            float2 v3 = *(const float2*)(q1p + kb * 16 + 8 + 2 * lr);
            float a0 = v0.x * c00 - v0.y * s00, b0 = v0.x * s00 + v0.y * c00;
            float a1 = v1.x * c10 - v1.y * s10, b1 = v1.x * s10 + v1.y * c10;
            float a2 = v2.x * c01 - v2.y * s01, b2 = v2.x * s01 + v2.y * c01;
            float a3 = v3.x * c11 - v3.y * s11, b3 = v3.x * s11 + v3.y * c11;
            split2(a0 * 0.125f, b0 * 0.125f, qaH[kb][0], qaL[kb][0]);
            split2(a1 * 0.125f, b1 * 0.125f, qaH[kb][1], qaL[kb][1]);
            split2(a2 * 0.125f, b2 * 0.125f, qaH[kb][2], qaL[kb][2]);
            split2(a3 * 0.125f, b3 * 0.125f, qaH[kb][3], qaL[kb][3]);
        }
    }

    float acc[8][4] = {};
    float m0 = -1e30f, m1 = -1e30f, l0 = 0.f, l1 = 0.f;
    const int ntiles = qb + 1;

    const unsigned aOff = (unsigned)(lane & 15) * ARS + (unsigned)(lane >> 4) * 16;
    const unsigned bOff = (unsigned)((lane >> 4) * 8 + (lane & 7)) * ARS
                        + (unsigned)((lane >> 3) & 1) * 16;

    auto issue_tile = [&](int kt) {
        const int kbase = kt * 64;
        unsigned sb = sb0 + (kt & 1) * ASTAGE;
        #pragma unroll
        for (int i = 0; i < 8; i++) {
            int c   = t + i * 128;                 // 0..1023
            int buf = c >> 9;                      // 0 K, 1 V
            int cc  = c & 511;
            int row = cc >> 3, q8 = cc & 7;
            const __half* src = kvh + (size_t)(b * SS + kbase + row) * 1024
                                    + buf * 512 + kh * 64 + q8 * 8;
            unsigned dst = sb + buf * ATILE + row * ARS + q8 * 16;
            asm volatile("cp.async.cg.shared.global [%0], [%1], 16;"
                         :: "r"(dst), "l"(src) : "memory");
        }
        asm volatile("cp.async.commit_group;" ::: "memory");
    };

    issue_tile(0);
    for (int kt = 0; kt < ntiles; kt++) {
        if (kt + 1 < ntiles) {
            issue_tile(kt + 1);
            asm volatile("cp.async.wait_group 1;" ::: "memory");
        } else {
            asm volatile("cp.async.wait_group 0;" ::: "memory");
        }
        __syncthreads();

        const unsigned stb = sb0 + (kt & 1) * ASTAGE;
        const int kbase = kt * 64;

        float s[8][4] = {};
        #pragma unroll
        for (int kb = 0; kb < 4; kb++) {
            unsigned kf[4][4];
            #pragma unroll
            for (int ng = 0; ng < 4; ng++) {
                unsigned ad = stb + (unsigned)(ng * 16) * ARS + kb * 32 + bOff;
                LDSM4(kf[ng][0], kf[ng][1], kf[ng][2], kf[ng][3], ad);
            }
            #pragma unroll
            for (int ng = 0; ng < 4; ng++) {
                F16MMA(s[ng*2],   qaH[kb], (kf[ng] + 0));
                F16MMA(s[ng*2],   qaL[kb], (kf[ng] + 0));
                F16MMA(s[ng*2+1], qaH[kb], (kf[ng] + 2));
                F16MMA(s[ng*2+1], qaL[kb], (kf[ng] + 2));
            }
        }

        if (kt == qb) {
            int row0 = qb * 64 + w * 16 + lq;
            #pragma unroll
            for (int ni = 0; ni < 8; ni++) {
                int col = kbase + ni * 8 + 2 * lr;
                if (col     > row0)     s[ni][0] = -1e30f;
                if (col + 1 > row0)     s[ni][1] = -1e30f;
                if (col     > row0 + 8) s[ni][2] = -1e30f;
                if (col + 1 > row0 + 8) s[ni][3] = -1e30f;
            }
        }

        float mt0 = -1e30f, mt1 = -1e30f;
        #pragma unroll
        for (int ni = 0; ni < 8; ni++) {
            mt0 = fmaxf(mt0, fmaxf(s[ni][0], s[ni][1]));
            mt1 = fmaxf(mt1, fmaxf(s[ni][2], s[ni][3]));
        }
        mt0 = fmaxf(mt0, __shfl_xor_sync(0xffffffffu, mt0, 1));
        mt0 = fmaxf(mt0, __shfl_xor_sync(0xffffffffu, mt0, 2));
        mt1 = fmaxf(mt1, __shfl_xor_sync(0xffffffffu, mt1, 1));
        mt1 = fmaxf(mt1, __shfl_xor_sync(0xffffffffu, mt1, 2));
        float mn0 = fmaxf(m0, mt0), mn1 = fmaxf(m1, mt1);
        float c0 = __expf(m0 - mn0), c1 = __expf(m1 - mn1);
        m0 = mn0; m1 = mn1;
        float rs0 = 0.f, rs1 = 0.f;
        #pragma unroll
        for (int ni = 0; ni < 8; ni++) {
            s[ni][0] = __expf(s[ni][0] - mn0);
            s[ni][1] = __expf(s[ni][1] - mn0);
            s[ni][2] = __expf(s[ni][2] - mn1);
            s[ni][3] = __expf(s[ni][3] - mn1);
            rs0 += s[ni][0] + s[ni][1];
            rs1 += s[ni][2] + s[ni][3];
        }
        rs0 += __shfl_xor_sync(0xffffffffu, rs0, 1);
        rs0 += __shfl_xor_sync(0xffffffffu, rs0, 2);
        rs1 += __shfl_xor_sync(0xffffffffu, rs1, 1);
        rs1 += __shfl_xor_sync(0xffffffffu, rs1, 2);
        l0 = l0 * c0 + rs0;
        l1 = l1 * c1 + rs1;
        #pragma unroll
        for (int dn = 0; dn < 8; dn++) {
            acc[dn][0] *= c0; acc[dn][1] *= c0;
            acc[dn][2] *= c1; acc[dn][3] *= c1;
        }

        #pragma unroll
        for (int kb = 0; kb < 4; kb++) {
            unsigned aPH[4], aPL[4];
            split2(s[2*kb][0],   s[2*kb][1],   aPH[0], aPL[0]);
            split2(s[2*kb][2],   s[2*kb][3],   aPH[1], aPL[1]);
            split2(s[2*kb+1][0], s[2*kb+1][1], aPH[2], aPL[2]);
            split2(s[2*kb+1][2], s[2*kb+1][3], aPH[3], aPL[3]);
            #pragma unroll
            for (int dn = 0; dn < 4; dn++) {
                unsigned vf[4];
                unsigned ad = stb + ATILE + (unsigned)(kb * 16) * ARS
                            + (unsigned)(dn * 16) * 2 + aOff;
                LDSM4T(vf[0], vf[1], vf[2], vf[3], ad);
                float* acc0 = acc[dn * 2];
                float* acc1 = acc[dn * 2 + 1];
                F16MMA(acc0, aPH, (vf + 0));
                F16MMA(acc0, aPL, (vf + 0));
                F16MMA(acc1, aPH, (vf + 2));
                F16MMA(acc1, aPL, (vf + 2));
            }
        }
        __syncthreads();
    }

    float inv0 = 1.f / l0, inv1 = 1.f / l1;
    int row0 = qb * 64 + w * 16 + lq;
    size_t b0 = ((size_t)(b * SS + row0) * HH + hd) * DK;
    size_t b1 = b0 + (size_t)8 * HH * DK;
    #pragma unroll
    for (int dn = 0; dn < 8; dn++) {
        int d = dn * 8 + 2 * lr;
        unsigned h_, l_;
        split2(acc[dn][0] * inv0, acc[dn][1] * inv0, h_, l_);
        *(unsigned*)(OH + b0 + d) = h_;
        *(unsigned*)(OL + b0 + d) = l_;
        split2(acc[dn][2] * inv1, acc[dn][3] * inv1, h_, l_);
        *(unsigned*)(OH + b1 + d) = h_;
        *(unsigned*)(OL + b1 + d) = l_;
    }
}

// ========== fp16 GEMM: compensated A (hi+lo), fp16 weights (2-MMA) =========
// C[M,N] = (AH+AL)[M][K] @ W[N][K]^T (+bias)(+residual), fp32 out.
// Block tile 128xBN (BN=128/256), 256 threads, 8 warps (2x4), warp 64x(BN/4).
#define G_BK 32
#define G_RS 80

template<int BN>
__global__ __launch_bounds__(256)
void gemm_bb_kernel(const __half* __restrict__ AH_, const __half* __restrict__ AL_,
                    const __half* __restrict__ BH_,
                    const float* __restrict__ bias, const float* __restrict__ res,
                    float* __restrict__ C, int Nd, int Kd) {
    constexpr int NG      = BN / 64;
    constexpr unsigned OFF_AL = 128 * G_RS;
    constexpr unsigned OFF_BH = 256 * G_RS;
    constexpr unsigned STAGE  = (256 + BN) * G_RS;
    constexpr int CH_B    = BN * 4;

    extern __shared__ char smem[];
    const unsigned sbase = smem_u32(smem);
    const int t    = threadIdx.x;
    const int lane = t & 31;
    const int warp = t >> 5;
    const int wm   = warp >> 2;
    const int wn   = warp & 3;
    const int bm   = blockIdx.y * 128;
    const int bn   = blockIdx.x * BN;

    float acc[4][2 * NG][4] = {};
    const int nkt = Kd / G_BK;

    auto issue_stage = [&](int kt) {
        const int k0 = kt * G_BK;
        unsigned sb = sbase + (kt % 3) * STAGE;
        #pragma unroll
        for (int i = 0; i < 4; i++) {
            int c = t + i * 256;
            const __half* base = (c < 512) ? AH_ : AL_;
            unsigned offt = (c < 512) ? 0u : OFF_AL;
            int cc = c & 511;
            int row = cc >> 2, quad = cc & 3;
            const __half* src = base + (size_t)(bm + row) * Kd + k0 + quad * 8;
            unsigned dst = sb + offt + row * G_RS + quad * 16;
            asm volatile("cp.async.cg.shared.global [%0], [%1], 16;"
                         :: "r"(dst), "l"(src) : "memory");
        }
        #pragma unroll
        for (int i = 0; i < BN / 64; i++) {
            int c = t + i * 256;                   // 0..CH_B-1
            int row = c >> 2, quad = c & 3;
            const __half* src = BH_ + (size_t)(bn + row) * Kd + k0 + quad * 8;
            unsigned dst = sb + OFF_BH + row * G_RS + quad * 16;
            int vsz = (bn + row < Nd) ? 16 : 0;
            asm volatile("cp.async.cg.shared.global [%0], [%1], 16, %2;"
                         :: "r"(dst), "l"(src), "r"(vsz) : "memory");
        }
        asm volatile("cp.async.commit_group;" ::: "memory");
    };

    issue_stage(0);
    issue_stage(1);

    const int m0 = wm * 64;
    const int n0 = wn * (BN / 4);
    const int lq = lane >> 2;
    const int lr = lane & 3;
    const unsigned aRowOff = (unsigned)(lane & 15) * G_RS + (unsigned)(lane >> 4) * 16;
    const unsigned bRowOff = ((unsigned)((lane >> 4) * 8 + (lane & 7))) * G_RS
                           + (unsigned)((lane >> 3) & 1) * 16;

    for (int kt = 0; kt < nkt; kt++) {
        asm volatile("cp.async.wait_group 1;" ::: "memory");
        __syncthreads();
        if (kt + 2 < nkt) issue_stage(kt + 2);
        else asm volatile("cp.async.commit_group;" ::: "memory");

        const unsigned stb = sbase + (kt % 3) * STAGE;
        #pragma unroll
        for (int ks = 0; ks < 2; ks++) {
            unsigned aH[4][4], aL[4][4], bF[NG][4];
            const unsigned ksb = ks * 32;
            #pragma unroll
            for (int mi = 0; mi < 4; mi++) {
                unsigned ah = stb + (m0 + mi * 16) * G_RS + ksb + aRowOff;
                unsigned al = ah + OFF_AL;
                LDSM4(aH[mi][0], aH[mi][1], aH[mi][2], aH[mi][3], ah);
                LDSM4(aL[mi][0], aL[mi][1], aL[mi][2], aL[mi][3], al);
            }
            #pragma unroll
            for (int ng = 0; ng < NG; ng++) {
                unsigned bhh = stb + OFF_BH + (n0 + ng * 16) * G_RS + ksb + bRowOff;
                LDSM4(bF[ng][0], bF[ng][1], bF[ng][2], bF[ng][3], bhh);
            }
            #pragma unroll
            for (int mi = 0; mi < 4; mi++)
                #pragma unroll
                for (int ng = 0; ng < NG; ng++) {
                    float* acc0 = acc[mi][ng * 2];
                    float* acc1 = acc[mi][ng * 2 + 1];
                    F16MMA(acc0, aH[mi], (bF[ng] + 0));
                    F16MMA(acc0, aL[mi], (bF[ng] + 0));
                    F16MMA(acc1, aH[mi], (bF[ng] + 2));
                    F16MMA(acc1, aL[mi], (bF[ng] + 2));
                }
        }
    }

    #pragma unroll
    for (int mi = 0; mi < 4; mi++) {
        int row = bm + m0 + mi * 16 + lq;
        #pragma unroll
        for (int ni = 0; ni < 2 * NG; ni++) {
            int col = bn + n0 + ni * 8 + lr * 2;
            if (col < Nd) {
                float v0 = acc[mi][ni][0], v1 = acc[mi][ni][1];
                float v2 = acc[mi][ni][2], v3 = acc[mi][ni][3];
                if (bias) {
                    float bx = bias[col], by = bias[col + 1];
                    v0 += bx; v1 += by; v2 += bx; v3 += by;
                }
                size_t o0 = (size_t)row * Nd + col;
                size_t o1 = (size_t)(row + 8) * Nd + col;
                if (res) {
                    v0 += res[o0]; v1 += res[o0 + 1];
                    v2 += res[o1]; v3 += res[o1 + 1];
                }
                C[o0] = v0; C[o0 + 1] = v1;
                C[o1] = v2; C[o1 + 1] = v3;
            }
        }
    }
}

#define SM128 ((256 + 128) * G_RS * 3)    // 92160
#define SM256 ((256 + 256) * G_RS * 3)    // 122880

// ---------------- silu(f1)*f2 -> split ----------------
__global__ void silumul_split_kernel(const float* __restrict__ f1,
                                     const float* __restrict__ f2,
                                     __half* __restrict__ H,
                                     __half* __restrict__ L) {
    size_t i = (size_t)blockIdx.x * 256 + threadIdx.x;
    float2 a = ((const float2*)f1)[i];
    float2 b = ((const float2*)f2)[i];
    float g0 = a.x / (1.0f + __expf(-a.x)) * b.x;
    float g1 = a.y / (1.0f + __expf(-a.y)) * b.y;
    unsigned h_, l_;
    split2(g0, g1, h_, l_);
    ((unsigned*)H)[i] = h_;
    ((unsigned*)L)[i] = l_;
}

// ---------------- host driver ----------------
extern "C" void kernel_launch(void* const* d_in, const int* in_sizes, int n_in,
                              void* d_out, int out_size) {
    const int*   tokens = (const int*)  d_in[0];
    const float* emb    = (const float*)d_in[1];
    const float* wq = (const float*)d_in[2];
    const float* bq = (const float*)d_in[3];
    const float* wk = (const float*)d_in[4];
    const float* bk = (const float*)d_in[5];
    const float* wv = (const float*)d_in[6];
    const float* bv = (const float*)d_in[7];
    const float* wo = (const float*)d_in[8];
    const float* bo = (const float*)d_in[9];
    const float* w1 = (const float*)d_in[10];
    const float* b1 = (const float*)d_in[11];
    const float* w2 = (const float*)d_in[12];
    const float* b2 = (const float*)d_in[13];
    const float* w3 = (const float*)d_in[14];
    const float* b3 = (const float*)d_in[15];
    const float* g1 = (const float*)d_in[16];
    const float* g2 = (const float*)d_in[17];
    const float* gpost = (const float*)d_in[18];
    const float* fcos  = (const float*)d_in[19];
    const float* fsin  = (const float*)d_in[20];
    float* out = (float*)d_out;

    float *x, *q, *kv, *f1, *f2, *bkv;
    __half *hH, *hL, *oH, *oL, *kvh, *f1H, *f1L;
    __half *wqh, *wkvh, *woh, *w1h, *w2h, *w3h, *ebh;
    cudaGetSymbolAddress((void**)&x,   g_x);
    cudaGetSymbolAddress((void**)&q,   g_q);
    cudaGetSymbolAddress((void**)&kv,  g_kv);
    cudaGetSymbolAddress((void**)&f1,  g_f1);
    cudaGetSymbolAddress((void**)&f2,  g_f2);
    cudaGetSymbolAddress((void**)&bkv, g_bkv);
    cudaGetSymbolAddress((void**)&hH,  g_hH);   cudaGetSymbolAddress((void**)&hL,  g_hL);
    cudaGetSymbolAddress((void**)&oH,  g_oH);   cudaGetSymbolAddress((void**)&oL,  g_oL);
    cudaGetSymbolAddress((void**)&kvh, g_kvh);
    cudaGetSymbolAddress((void**)&f1H, g_f1H);  cudaGetSymbolAddress((void**)&f1L, g_f1L);
    cudaGetSymbolAddress((void**)&wqh, g_wq);
    cudaGetSymbolAddress((void**)&wkvh, g_wkv);
    cudaGetSymbolAddress((void**)&woh, g_wo);
    cudaGetSymbolAddress((void**)&w1h, g_w1);
    cudaGetSymbolAddress((void**)&w2h, g_w2);
    cudaGetSymbolAddress((void**)&w3h, g_w3);
    cudaGetSymbolAddress((void**)&ebh, g_eb);

    cudaFuncSetAttribute(gemm_bb_kernel<128>,
                         cudaFuncAttributeMaxDynamicSharedMemorySize, SM128);
    cudaFuncSetAttribute(gemm_bb_kernel<256>,
                         cudaFuncAttributeMaxDynamicSharedMemorySize, SM256);
    cudaFuncSetAttribute(attn_tc_kernel,
                         cudaFuncAttributeMaxDynamicSharedMemorySize, ASMEM);

    // ---- conversions (inside graph) ----
    esplit_kernel<<<(VV * DD) / (256 * 4), 256>>>(emb, ebh);
    bkv_kernel<<<NL, 512>>>(bk, bv, bkv);
    dim3 tb(32, 8);
    for (int l = 0; l < NL; l++) {
        tsplit_kernel<<<dim3(DD / 32, DD / 32), tb>>>(
            wq + (size_t)l * DD * DD, wqh + (size_t)l * DD * DD, DD, DD);
        tsplit_kernel<<<dim3(KVN / 32, DD / 32), tb>>>(
            wk + (size_t)l * DD * KVN, wkvh + (size_t)l * 1024 * DD, DD, KVN);
        tsplit_kernel<<<dim3(KVN / 32, DD / 32), tb>>>(
            wv + (size_t)l * DD * KVN,
            wkvh + (size_t)l * 1024 * DD + (size_t)512 * DD, DD, KVN);
        tsplit_kernel<<<dim3(DD / 32, DD / 32), tb>>>(
            wo + (size_t)l * DD * DD, woh + (size_t)l * DD * DD, DD, DD);
        tsplit_kernel<<<dim3(FD / 32, DD / 32), tb>>>(
            w1 + (size_t)l * DD * FD, w1h + (size_t)l * DD * FD, DD, FD);
        tsplit_kernel<<<dim3(FD / 32, DD / 32), tb>>>(
            w2 + (size_t)l * DD * FD, w2h + (size_t)l * DD * FD, DD, FD);
        tsplit_kernel<<<dim3(DD / 32, FD / 32), tb>>>(
            w3 + (size_t)l * FD * DD, w3h + (size_t)l * FD * DD, FD, DD);
    }

    embed_kernel<<<MM, 256>>>(tokens, emb, x);

    const int GY = MM / 128;    // 32
    for (int l = 0; l < NL; l++) {
        rmsnorm_split_kernel<<<MM, 256>>>(x, g1 + (size_t)l * DD, hH, hL);

        gemm_bb_kernel<256><<<dim3(DD / 256, GY), 256, SM256>>>(
            hH, hL, wqh + (size_t)l * DD * DD,
            bq + (size_t)l * DD, nullptr, q, DD, DD);
        gemm_bb_kernel<256><<<dim3(1024 / 256, GY), 256, SM256>>>(
            hH, hL, wkvh + (size_t)l * 1024 * DD,
            bkv + (size_t)l * 1024, nullptr, kv, 1024, DD);

        kvsplit_rope_kernel<<<MM, 256>>>(kv, fcos, fsin, kvh);

        attn_tc_kernel<<<dim3(SS / 64, HH, BB), 128, ASMEM>>>(
            q, kvh, fcos, fsin, oH, oL);

        gemm_bb_kernel<256><<<dim3(DD / 256, GY), 256, SM256>>>(
            oH, oL, woh + (size_t)l * DD * DD,
            bo + (size_t)l * DD, x, x, DD, DD);

        rmsnorm_split_kernel<<<MM, 256>>>(x, g2 + (size_t)l * DD, hH, hL);

        int gnx = (FD + 255) / 256;   // 11
        gemm_bb_kernel<256><<<dim3(gnx, GY), 256, SM256>>>(
            hH, hL, w1h + (size_t)l * DD * FD,
            b1 + (size_t)l * FD, nullptr, f1, FD, DD);
        gemm_bb_kernel<256><<<dim3(gnx, GY), 256, SM256>>>(
            hH, hL, w2h + (size_t)l * DD * FD,
            b2 + (size_t)l * FD, nullptr, f2, FD, DD);

        silumul_split_kernel<<<(MM * (FD / 2)) / 256, 256>>>(f1, f2, f1H, f1L);

        gemm_bb_kernel<256><<<dim3(DD / 256, GY), 256, SM256>>>(
            f1H, f1L, w3h + (size_t)l * FD * DD,
            b3 + (size_t)l * DD, x, x, DD, FD);
    }

    rmsnorm_split_kernel<<<MM, 256>>>(x, gpost, hH, hL);
    gemm_bb_kernel<256><<<dim3(VV / 256, GY), 256, SM256>>>(
        hH, hL, ebh, nullptr, nullptr, out, VV, DD);
}